// round 10
// baseline (speedup 1.0000x reference)
#include <cuda_runtime.h>
#include <cuda_bf16.h>
#include <cuda_fp16.h>
#include <math.h>
#include <stdint.h>

#define VOCAB 32000
#define EMB   300
#define NFLT  100
#define HID   256
#define BB    32
#define TT    64
#define LL    48
#define NCOL  1200
#define BT    (BB*TT)

#define KTOT  960
#define NPAD  1280
#define MTILES 250
#define NTILES 10

// ---------------- device scratch ----------------
__device__ __align__(16) __half g_P[(size_t)VOCAB * NCOL];          // fp16 projection (76.8 MB)
__device__ __align__(16) __nv_bfloat16 g_A2[(size_t)VOCAB * KTOT];
__device__ __align__(16) __nv_bfloat16 g_B2[(size_t)NPAD * KTOT];
__device__ float g_rin[BT * 300];
__device__ float g_XG[2 * TT * 1024 * BB];
__device__ float g_HS[2 * TT * HID * BB];

__device__ __forceinline__ float sigf(float x) { return 1.0f / (1.0f + expf(-x)); }

__device__ __forceinline__ uint32_t smem_u32(const void* p) {
    uint32_t a;
    asm("{ .reg .u64 t; cvta.to.shared.u64 t, %1; cvt.u32.u64 %0, t; }" : "=r"(a) : "l"(p));
    return a;
}
#define CP_ASYNC16(d, s) asm volatile("cp.async.cg.shared.global [%0], [%1], 16;" :: "r"(d), "l"(s))
#define CP_COMMIT()      asm volatile("cp.async.commit_group;" ::: "memory")
#define CP_WAIT(n)       asm volatile("cp.async.wait_group %0;" :: "n"(n) : "memory")
#define LDMX4(r0, r1, r2, r3, addr) \
    asm volatile("ldmatrix.sync.aligned.m8n8.x4.shared.b16 {%0,%1,%2,%3}, [%4];" \
                 : "=r"(r0), "=r"(r1), "=r"(r2), "=r"(r3) : "r"(addr))
#define MMA16816(c, a, b) \
    asm volatile("mma.sync.aligned.m16n8k16.row.col.f32.bf16.bf16.f32 " \
                 "{%0,%1,%2,%3}, {%4,%5,%6,%7}, {%8,%9}, {%0,%1,%2,%3};" \
                 : "+f"((c)[0]), "+f"((c)[1]), "+f"((c)[2]), "+f"((c)[3]) \
                 : "r"((a)[0]), "r"((a)[1]), "r"((a)[2]), "r"((a)[3]), "r"((b)[0]), "r"((b)[1]))

#define CLUSTER_ARRIVE() asm volatile("barrier.cluster.arrive.aligned;" ::: "memory")
#define CLUSTER_WAIT()   asm volatile("barrier.cluster.wait.aligned;" ::: "memory")

__device__ __forceinline__ void dsmem_st_b16(uint32_t laddr, uint32_t rank, unsigned short v) {
    asm volatile(
        "{\n\t.reg .b32 ra;\n\t"
        "mapa.shared::cluster.u32 ra, %0, %1;\n\t"
        "st.shared::cluster.b16 [ra], %2;\n\t}"
        :: "r"(laddr), "r"(rank), "h"(v) : "memory");
}

// ---------------- build A2 = [Ahi | Ahi | Alo] ----------------
__global__ void convA_kernel(const float* __restrict__ emb) {
    int idx = blockIdx.x * blockDim.x + threadIdx.x;
    if (idx >= VOCAB * 160) return;
    int m  = idx / 160;
    int k2 = idx % 160;
    int k  = k2 * 2;
    float v0 = (k     < EMB) ? __ldg(&emb[(size_t)m * EMB + k])     : 0.0f;
    float v1 = (k + 1 < EMB) ? __ldg(&emb[(size_t)m * EMB + k + 1]) : 0.0f;
    __nv_bfloat16 h0 = __float2bfloat16(v0), h1 = __float2bfloat16(v1);
    __nv_bfloat16 l0 = __float2bfloat16(v0 - __bfloat162float(h0));
    __nv_bfloat16 l1 = __float2bfloat16(v1 - __bfloat162float(h1));
    uint32_t hp = (uint32_t)reinterpret_cast<unsigned short&>(h0) |
                  ((uint32_t)reinterpret_cast<unsigned short&>(h1) << 16);
    uint32_t lp = (uint32_t)reinterpret_cast<unsigned short&>(l0) |
                  ((uint32_t)reinterpret_cast<unsigned short&>(l1) << 16);
    uint32_t* A = (uint32_t*)g_A2;
    size_t base = (size_t)m * 480;
    A[base + k2]       = hp;
    A[base + 160 + k2] = hp;
    A[base + 320 + k2] = lp;
}

// ---------------- build B2 = [Bhi | Blo | Bhi] ----------------
__global__ void convB_kernel(const float* __restrict__ w3, const float* __restrict__ w4,
                             const float* __restrict__ w5) {
    int idx = blockIdx.x * blockDim.x + threadIdx.x;
    if (idx >= NPAD * 160) return;
    int n  = idx / 160;
    int k2 = idx % 160;
    int k0 = k2 * 2;
    float v0 = 0.0f, v1 = 0.0f;
    if (n < NCOL) {
        int c = n;
#pragma unroll
        for (int q = 0; q < 2; q++) {
            int k = k0 + q;
            float v = 0.0f;
            if (k < EMB) {
                if (c < 300)      { int fk = c / 100;        int nf = c % 100;        v = __ldg(&w3[((size_t)nf * EMB + k) * 3 + fk]); }
                else if (c < 700) { int c2 = c - 300; int fk = c2 / 100; int nf = c2 % 100; v = __ldg(&w4[((size_t)nf * EMB + k) * 4 + fk]); }
                else              { int c2 = c - 700; int fk = c2 / 100; int nf = c2 % 100; v = __ldg(&w5[((size_t)nf * EMB + k) * 5 + fk]); }
            }
            if (q == 0) v0 = v; else v1 = v;
        }
    }
    __nv_bfloat16 h0 = __float2bfloat16(v0), h1 = __float2bfloat16(v1);
    __nv_bfloat16 l0 = __float2bfloat16(v0 - __bfloat162float(h0));
    __nv_bfloat16 l1 = __float2bfloat16(v1 - __bfloat162float(h1));
    uint32_t hp = (uint32_t)reinterpret_cast<unsigned short&>(h0) |
                  ((uint32_t)reinterpret_cast<unsigned short&>(h1) << 16);
    uint32_t lp = (uint32_t)reinterpret_cast<unsigned short&>(l0) |
                  ((uint32_t)reinterpret_cast<unsigned short&>(l1) << 16);
    uint32_t* B = (uint32_t*)g_B2;
    size_t base = (size_t)n * 480;
    B[base + k2]       = hp;
    B[base + 160 + k2] = lp;
    B[base + 320 + k2] = hp;
}

// ---------------- HMMA GEMM (P) ----------------
__device__ __forceinline__ void load_chunk(uint32_t sAb, uint32_t sBb, int bm, int bn,
                                           int kk, int tid) {
    const uint8_t* Ab = (const uint8_t*)g_A2;
    const uint8_t* Bb = (const uint8_t*)g_B2;
#pragma unroll
    for (int i = 0; i < 4; i++) {
        int id = tid + i * 256;
        int r = id >> 3, c = id & 7;
        uint32_t d = sAb + r * 128 + ((c ^ (r & 7)) << 4);
        CP_ASYNC16(d, Ab + (size_t)(bm + r) * (KTOT * 2) + kk * 2 + c * 16);
    }
#pragma unroll
    for (int i = 0; i < 4; i++) {
        int id = tid + i * 256;
        int r = id >> 3, c = id & 7;
        uint32_t d = sBb + r * 128 + ((c ^ (r & 7)) << 4);
        CP_ASYNC16(d, Bb + (size_t)(bn + r) * (KTOT * 2) + kk * 2 + c * 16);
    }
}

__global__ void __launch_bounds__(256, 2) pgemm_mma_kernel() {
    extern __shared__ __align__(128) uint8_t dyn[];
    uint32_t sbase = smem_u32(dyn);
    int tid  = threadIdx.x;
    int wid  = tid >> 5, lane = tid & 31;
    int m0   = (wid & 1) * 64;
    int n0   = (wid >> 1) * 32;
    int bm   = blockIdx.y * 128;
    int bn   = blockIdx.x * 128;

    float acc[4][4][4];
#pragma unroll
    for (int i = 0; i < 4; i++)
#pragma unroll
        for (int j = 0; j < 4; j++)
#pragma unroll
            for (int q = 0; q < 4; q++) acc[i][j][q] = 0.0f;

    load_chunk(sbase, sbase + 16384, bm, bn, 0, tid);
    CP_COMMIT();

#pragma unroll 1
    for (int it = 0; it < 15; it++) {
        if (it < 14) {
            uint32_t nb = sbase + ((it + 1) & 1) * 32768;
            load_chunk(nb, nb + 16384, bm, bn, (it + 1) * 64, tid);
            CP_COMMIT();
            CP_WAIT(1);
        } else {
            CP_WAIT(0);
        }
        __syncthreads();

        uint32_t sAb = sbase + (it & 1) * 32768;
        uint32_t sBb = sAb + 16384;
#pragma unroll
        for (int ks = 0; ks < 4; ks++) {
            uint32_t a[4][4];
#pragma unroll
            for (int mf = 0; mf < 4; mf++) {
                int row = m0 + mf * 16 + (lane & 15);
                int ch  = ks * 2 + (lane >> 4);
                uint32_t addr = sAb + row * 128 + ((ch ^ (row & 7)) << 4);
                LDMX4(a[mf][0], a[mf][1], a[mf][2], a[mf][3], addr);
            }
            uint32_t b[4][2];
#pragma unroll
            for (int p = 0; p < 2; p++) {
                int sel = lane >> 3;
                int row = n0 + p * 16 + ((sel >> 1) << 3) + (lane & 7);
                int ch  = ks * 2 + (sel & 1);
                uint32_t addr = sBb + row * 128 + ((ch ^ (row & 7)) << 4);
                uint32_t r0, r1, r2, r3;
                LDMX4(r0, r1, r2, r3, addr);
                b[p * 2][0] = r0; b[p * 2][1] = r1;
                b[p * 2 + 1][0] = r2; b[p * 2 + 1][1] = r3;
            }
#pragma unroll
            for (int mf = 0; mf < 4; mf++)
#pragma unroll
                for (int nf = 0; nf < 4; nf++)
                    MMA16816(acc[mf][nf], a[mf], b[nf]);
        }
        __syncthreads();
    }

#pragma unroll
    for (int mf = 0; mf < 4; mf++) {
        int row0 = bm + m0 + mf * 16 + (lane >> 2);
#pragma unroll
        for (int nf = 0; nf < 4; nf++) {
            int col = bn + n0 + nf * 8 + 2 * (lane & 3);
            if (col < NCOL) {
                *(__half2*)(g_P + (size_t)row0 * NCOL + col) =
                    __floats2half2_rn(acc[mf][nf][0], acc[mf][nf][1]);
                *(__half2*)(g_P + (size_t)(row0 + 8) * NCOL + col) =
                    __floats2half2_rn(acc[mf][nf][2], acc[mf][nf][3]);
            }
        }
    }
}

// ---------------- conv gather (fp16 P, half2 per thread) ----------------
__global__ void conv_gather_kernel(const int* __restrict__ dia,
                                   const float* __restrict__ b3,
                                   const float* __restrict__ b4,
                                   const float* __restrict__ b5) {
    int bt = blockIdx.x;
    __shared__ int tok[LL];
    int tid = threadIdx.x;
    if (tid < LL) tok[tid] = dia[bt * LL + tid] * NCOL;
    __syncthreads();
    if (tid >= 50) return;
    int nf = tid * 2;
    const __half* P = g_P;

    float mx3 = -1e30f, my3 = -1e30f;
    for (int p = 0; p < 46; p++) {
        float2 a = __half22float2(*(const __half2*)(P + (size_t)tok[p]     + nf));
        float2 b = __half22float2(*(const __half2*)(P + (size_t)tok[p + 1] + 100 + nf));
        float2 c = __half22float2(*(const __half2*)(P + (size_t)tok[p + 2] + 200 + nf));
        mx3 = fmaxf(mx3, a.x + b.x + c.x);
        my3 = fmaxf(my3, a.y + b.y + c.y);
    }
    g_rin[bt * 300 + nf]     = fmaxf(mx3 + b3[nf], 0.0f);
    g_rin[bt * 300 + nf + 1] = fmaxf(my3 + b3[nf + 1], 0.0f);

    float mx4 = -1e30f, my4 = -1e30f;
    for (int p = 0; p < 45; p++) {
        float2 a = __half22float2(*(const __half2*)(P + (size_t)tok[p]     + 300 + nf));
        float2 b = __half22float2(*(const __half2*)(P + (size_t)tok[p + 1] + 400 + nf));
        float2 c = __half22float2(*(const __half2*)(P + (size_t)tok[p + 2] + 500 + nf));
        float2 d = __half22float2(*(const __half2*)(P + (size_t)tok[p + 3] + 600 + nf));
        mx4 = fmaxf(mx4, a.x + b.x + c.x + d.x);
        my4 = fmaxf(my4, a.y + b.y + c.y + d.y);
    }
    g_rin[bt * 300 + 100 + nf]     = fmaxf(mx4 + b4[nf], 0.0f);
    g_rin[bt * 300 + 100 + nf + 1] = fmaxf(my4 + b4[nf + 1], 0.0f);

    float mx5 = -1e30f, my5 = -1e30f;
    for (int p = 0; p < 44; p++) {
        float2 a = __half22float2(*(const __half2*)(P + (size_t)tok[p]     + 700 + nf));
        float2 b = __half22float2(*(const __half2*)(P + (size_t)tok[p + 1] + 800 + nf));
        float2 c = __half22float2(*(const __half2*)(P + (size_t)tok[p + 2] + 900 + nf));
        float2 d = __half22float2(*(const __half2*)(P + (size_t)tok[p + 3] + 1000 + nf));
        float2 e = __half22float2(*(const __half2*)(P + (size_t)tok[p + 4] + 1100 + nf));
        mx5 = fmaxf(mx5, a.x + b.x + c.x + d.x + e.x);
        my5 = fmaxf(my5, a.y + b.y + c.y + d.y + e.y);
    }
    g_rin[bt * 300 + 200 + nf]     = fmaxf(mx5 + b5[nf], 0.0f);
    g_rin[bt * 300 + 200 + nf + 1] = fmaxf(my5 + b5[nf + 1], 0.0f);
}

// ---------------- xg GEMM ----------------
__global__ void xg_gemm_kernel(const float* __restrict__ wih_f, const float* __restrict__ wih_r,
                               const float* __restrict__ bih_f, const float* __restrict__ bhh_f,
                               const float* __restrict__ bih_r, const float* __restrict__ bhh_r) {
    const int K = 300;
    __shared__ float sA[16][132];
    __shared__ float sB[16][68];
    int dir = blockIdx.z;
    const float* W  = dir ? wih_r : wih_f;
    const float* bi = dir ? bih_r : bih_f;
    const float* bh = dir ? bhh_r : bhh_f;
    int bm = blockIdx.y * 128;
    int bn = blockIdx.x * 64;
    int tid = threadIdx.x;
    int tx = tid & 15, ty = tid >> 4;
    float acc[8][4] = {};
    for (int kk = 0; kk < K; kk += 16) {
        int ak = tid & 15, am = tid >> 4;
        int gk = kk + ak;
#pragma unroll
        for (int i = 0; i < 8; i++) {
            int m  = am + i * 16;
            int gm = bm + m;
            int t  = gm >> 5, bb = gm & 31;
            int st = dir ? (63 - t) : t;
            sA[ak][m] = (gk < K) ? __ldg(&g_rin[(bb * 64 + st) * 300 + gk]) : 0.0f;
        }
        int wk = tid & 15, wn = tid >> 4;
#pragma unroll
        for (int i = 0; i < 4; i++) {
            int n   = wn + i * 16;
            int gkb = kk + wk;
            sB[wk][n] = (gkb < K) ? __ldg(&W[(bn + n) * 300 + gkb]) : 0.0f;
        }
        __syncthreads();
#pragma unroll
        for (int k = 0; k < 16; k++) {
            float4 a0 = *(const float4*)&sA[k][ty * 8];
            float4 a1 = *(const float4*)&sA[k][ty * 8 + 4];
            float4 b0 = *(const float4*)&sB[k][tx * 4];
            float ra[8] = {a0.x, a0.y, a0.z, a0.w, a1.x, a1.y, a1.z, a1.w};
            float rb[4] = {b0.x, b0.y, b0.z, b0.w};
#pragma unroll
            for (int i = 0; i < 8; i++)
#pragma unroll
                for (int j = 0; j < 4; j++) acc[i][j] += ra[i] * rb[j];
        }
        __syncthreads();
    }
#pragma unroll
    for (int i = 0; i < 8; i++) {
        int gm = bm + ty * 8 + i;
        int t = gm >> 5, bb = gm & 31;
#pragma unroll
        for (int j = 0; j < 4; j++) {
            int g = bn + tx * 4 + j;
            g_XG[(((size_t)dir * 64 + t) * 1024 + g) * 32 + bb] =
                acc[i][j] + __ldg(&bi[g]) + __ldg(&bh[g]);
        }
    }
}

// ================= HMMA cluster BiLSTM v3 =================
// 4 clusters (dir x batch-half16) x 8 CTAs (j-slice of 32 -> 128 gate-rows)
// Warps N-split only (16 gate-rows each, full K) -> no cross-warp reduce.
// h' tile double-buffered bf16 hi/lo; finalists store remote bf16 directly.
#define LOFF_W    0                  // 131072 B
#define LOFF_HP   131072             // 2 bufs x 16384 B
#define LOFF_SG   163840             // 16 x 132 floats = 8448 B
#define LSM_BYTES 172288

__device__ __forceinline__ uint32_t hp_off(int buf, int b, int k) {
    int chunk = k >> 6;
    int byte  = (k & 63) * 2;
    int c16   = byte >> 4;
    return (uint32_t)(LOFF_HP + buf * 16384 + chunk * 2048 + b * 128 +
                      (((c16 ^ (b & 7)) << 4) | (byte & 15)));
}
__device__ __forceinline__ uint32_t w_off(int row, int chunk, int k) {
    int byte = k * 2;
    int c16  = byte >> 4;
    return (uint32_t)(LOFF_W + chunk * 16384 + row * 128 + (((c16 ^ (row & 7)) << 4) | (byte & 15)));
}

__global__ void __launch_bounds__(256, 1) __cluster_dims__(8, 1, 1)
lstm_mma_kernel(const float* __restrict__ whh_f, const float* __restrict__ whh_r) {
    extern __shared__ __align__(128) uint8_t lsm[];
    uint32_t sb = smem_u32(lsm);
    float* sG = (float*)(lsm + LOFF_SG);

    int tid = threadIdx.x;
    int w   = tid >> 5, lane = tid & 31;
    uint32_t rank;
    asm("mov.u32 %0, %%cluster_ctarank;" : "=r"(rank));
    int cid = blockIdx.x >> 3;
    int dir = cid >> 1;
    int bg  = cid & 1;
    int j0  = (int)rank * 32;
    const float* whh = dir ? whh_r : whh_f;
    const float* xg_glob = g_XG;

    // ---- load W' (once): rows 0..127 = jl*4+g ; chunks 0-3 hi, 4-7 lo ----
    for (int idx = tid; idx < 32768; idx += 256) {
        int row = idx >> 8;
        int k   = idx & 255;
        int jl = row >> 2, g = row & 3;
        float v = __ldg(&whh[(size_t)(g * 256 + j0 + jl) * 256 + k]);
        __nv_bfloat16 hi = __float2bfloat16(v);
        __nv_bfloat16 lo = __float2bfloat16(v - __bfloat162float(hi));
        *(__nv_bfloat16*)(lsm + w_off(row, k >> 6, k & 63))       = hi;
        *(__nv_bfloat16*)(lsm + w_off(row, (k >> 6) + 4, k & 63)) = lo;
    }
    // zero both h' buffers
    for (int i = tid; i < 32768 / 4; i += 256) ((uint32_t*)(lsm + LOFF_HP))[i] = 0;
    __syncthreads();
    CLUSTER_ARRIVE();
    CLUSTER_WAIT();

    int n0 = w * 16;                   // this warp's 16 gate-rows

    // finalist mapping: p = tid + pp*256 -> jl = p>>4, b = p&15
    int fjl[2], fb[2], fgj[2], fgb[2];
#pragma unroll
    for (int pp = 0; pp < 2; pp++) {
        int p = tid + pp * 256;
        fjl[pp] = p >> 4;
        fb[pp]  = p & 15;
        fgj[pp] = j0 + fjl[pp];
        fgb[pp] = bg * 16 + fb[pp];
    }
    float cst[2] = {0.0f, 0.0f};

    const int passW[3] = {0, 0, 4};    // W chunk group: hi, hi, lo
    const int passH[3] = {0, 4, 0};    // h chunk group: hi, lo, hi

    for (int s = 0; s < 64; s++) {
        int rbuf = s & 1;
        int wbuf = rbuf ^ 1;

        // ---- phase 0: prefetch XG ----
        float xai[2], xaf[2], xag[2], xao[2];
        {
            size_t xbase = (((size_t)dir * 64 + s) * 1024) * 32;
#pragma unroll
            for (int pp = 0; pp < 2; pp++) {
                xai[pp] = __ldg(&xg_glob[xbase + (size_t)(0   + fgj[pp]) * 32 + fgb[pp]]);
                xaf[pp] = __ldg(&xg_glob[xbase + (size_t)(256 + fgj[pp]) * 32 + fgb[pp]]);
                xag[pp] = __ldg(&xg_glob[xbase + (size_t)(512 + fgj[pp]) * 32 + fgb[pp]]);
                xao[pp] = __ldg(&xg_glob[xbase + (size_t)(768 + fgj[pp]) * 32 + fgb[pp]]);
            }
        }

        // ---- phase 1: HMMA (16 gate-rows, full K=768) ----
        float acc[2][4];
#pragma unroll
        for (int nf = 0; nf < 2; nf++)
#pragma unroll
            for (int q = 0; q < 4; q++) acc[nf][q] = 0.0f;

#pragma unroll
        for (int ps = 0; ps < 3; ps++) {
#pragma unroll
            for (int cc = 0; cc < 4; cc++) {
                uint32_t wbase = sb + LOFF_W + (passW[ps] + cc) * 16384;
                uint32_t hbase = sb + LOFF_HP + rbuf * 16384 + (passH[ps] & 4 ? 0 : 0) * 0;
                // h chunk within buffer: for lo pass (passH=4) use chunks 4..7? h' buffer
                // holds hi in chunks 0-3 and lo in chunks 4-7 of a 16KB buffer:
                hbase = sb + hp_off(rbuf, 0, 0) + ((passH[ps] >> 2) * 8192) + cc * 2048;
#pragma unroll
                for (int ks = 0; ks < 4; ks++) {
                    uint32_t a[4];
                    {
                        int row = lane & 15;
                        int ch  = ks * 2 + (lane >> 4);
                        uint32_t addr = hbase + row * 128 + ((ch ^ (row & 7)) << 4);
                        LDMX4(a[0], a[1], a[2], a[3], addr);
                    }
                    uint32_t b[2][2];
                    {
                        int sel = lane >> 3;
                        int row = n0 + ((sel >> 1) << 3) + (lane & 7);
                        int ch  = ks * 2 + (sel & 1);
                        uint32_t addr = wbase + row * 128 + ((ch ^ (row & 7)) << 4);
                        uint32_t r0, r1, r2, r3;
                        LDMX4(r0, r1, r2, r3, addr);
                        b[0][0] = r0; b[0][1] = r1;
                        b[1][0] = r2; b[1][1] = r3;
                    }
                    MMA16816(acc[0], a, b[0]);
                    MMA16816(acc[1], a, b[1]);
                }
            }
        }

        // ---- phase 2: write gate buffer (no reduce needed) ----
        {
            int rowb = lane >> 2;
            int colb = n0 + 2 * (lane & 3);
#pragma unroll
            for (int nf = 0; nf < 2; nf++) {
                int col = colb + nf * 8;
                sG[rowb * 132 + col]           = acc[nf][0];
                sG[rowb * 132 + col + 1]       = acc[nf][1];
                sG[(rowb + 8) * 132 + col]     = acc[nf][2];
                sG[(rowb + 8) * 132 + col + 1] = acc[nf][3];
            }
        }
        __syncthreads();

        // ---- phase 3: gates, cell update, direct remote bf16 stores ----
#pragma unroll
        for (int pp = 0; pp < 2; pp++) {
            const float* gr = sG + fb[pp] * 132 + fjl[pp] * 4;
            float ai = gr[0] + xai[pp];
            float af = gr[1] + xaf[pp];
            float ag = gr[2] + xag[pp];
            float ao = gr[3] + xao[pp];

            float iv = sigf(ai), fv = sigf(af), gv = tanhf(ag), ov = sigf(ao);
            cst[pp] = fv * cst[pp] + iv * gv;
            float h = ov * tanhf(cst[pp]);

            __nv_bfloat16 hi = __float2bfloat16(h);
            __nv_bfloat16 lo = __float2bfloat16(h - __bfloat162float(hi));
            unsigned short hu = reinterpret_cast<unsigned short&>(hi);
            unsigned short lu = reinterpret_cast<unsigned short&>(lo);
            uint32_t hoff = sb + hp_off(wbuf, fb[pp], fgj[pp]);
            uint32_t loff = sb + hp_off(wbuf, fb[pp], 256 + fgj[pp]);
#pragma unroll
            for (uint32_t tr = 0; tr < 8; tr++) {
                dsmem_st_b16(hoff, tr, hu);
                dsmem_st_b16(loff, tr, lu);
            }

            int tout = dir ? (63 - s) : s;
            g_HS[(((size_t)dir * 64 + tout) * HID + fgj[pp]) * 32 + fgb[pp]] = h;
        }

        // ---- phase 4: cluster barrier (h' buffers complete everywhere) ----
        CLUSTER_ARRIVE();
        CLUSTER_WAIT();
    }
}

// ---------------- head ----------------
__global__ void head_kernel(const float* __restrict__ hw, const float* __restrict__ hb,
                            float* __restrict__ out) {
    int t = blockIdx.x;
    int tid = threadIdx.x;
    int b  = tid & 31;
    int og = tid >> 5;
    const float* hf = g_HS + (size_t)(t * HID) * 32;
    const float* hr = g_HS + (size_t)((64 + t) * HID) * 32;
    float a0 = 0.f, a1 = 0.f, a2 = 0.f, a3 = 0.f;
    int o = og * 4;
    for (int h = 0; h < HID; h++) {
        float vf = __ldg(&hf[h * 32 + b]);
        float vr = __ldg(&hr[h * 32 + b]);
        a0 += vf * __ldg(&hw[(o + 0) * 512 + h]) + vr * __ldg(&hw[(o + 0) * 512 + 256 + h]);
        a1 += vf * __ldg(&hw[(o + 1) * 512 + h]) + vr * __ldg(&hw[(o + 1) * 512 + 256 + h]);
        a2 += vf * __ldg(&hw[(o + 2) * 512 + h]) + vr * __ldg(&hw[(o + 2) * 512 + 256 + h]);
        a3 += vf * __ldg(&hw[(o + 3) * 512 + h]) + vr * __ldg(&hw[(o + 3) * 512 + 256 + h]);
    }
    size_t base = ((size_t)b * 64 + t) * 32 + o;
    out[base + 0] = sigf(a0 + __ldg(&hb[o + 0]));
    out[base + 1] = sigf(a1 + __ldg(&hb[o + 1]));
    out[base + 2] = sigf(a2 + __ldg(&hb[o + 2]));
    out[base + 3] = sigf(a3 + __ldg(&hb[o + 3]));
}

// ---------------- launch ----------------
extern "C" void kernel_launch(void* const* d_in, const int* in_sizes, int n_in,
                              void* d_out, int out_size) {
    const int*   dialogue = (const int*)d_in[0];
    const float* emb   = (const float*)d_in[1];
    const float* w3    = (const float*)d_in[2];
    const float* b3    = (const float*)d_in[3];
    const float* w4    = (const float*)d_in[4];
    const float* b4    = (const float*)d_in[5];
    const float* w5    = (const float*)d_in[6];
    const float* b5    = (const float*)d_in[7];
    const float* wih_f = (const float*)d_in[8];
    const float* whh_f = (const float*)d_in[9];
    const float* bih_f = (const float*)d_in[10];
    const float* bhh_f = (const float*)d_in[11];
    const float* wih_r = (const float*)d_in[12];
    const float* whh_r = (const float*)d_in[13];
    const float* bih_r = (const float*)d_in[14];
    const float* bhh_r = (const float*)d_in[15];
    const float* hw    = (const float*)d_in[16];
    const float* hb    = (const float*)d_in[17];
    float* out = (float*)d_out;

    cudaFuncSetAttribute(pgemm_mma_kernel, cudaFuncAttributeMaxDynamicSharedMemorySize, 65536);
    cudaFuncSetAttribute(lstm_mma_kernel, cudaFuncAttributeMaxDynamicSharedMemorySize, LSM_BYTES);

    convA_kernel<<<(VOCAB * 160 + 255) / 256, 256>>>(emb);
    convB_kernel<<<(NPAD * 160 + 255) / 256, 256>>>(w3, w4, w5);

    dim3 gP(NTILES, MTILES);
    pgemm_mma_kernel<<<gP, 256, 65536>>>();

    conv_gather_kernel<<<BT, 64>>>(dialogue, b3, b4, b5);

    dim3 gX(16, 16, 2);
    xg_gemm_kernel<<<gX, 256>>>(wih_f, wih_r, bih_f, bhh_f, bih_r, bhh_r);

    lstm_mma_kernel<<<32, 256, LSM_BYTES>>>(whh_f, whh_r);

    head_kernel<<<TT, 256>>>(hw, hb, out);
}

// round 11
// speedup vs baseline: 1.1038x; 1.1038x over previous
#include <cuda_runtime.h>
#include <cuda_bf16.h>
#include <cuda_fp16.h>
#include <math.h>
#include <stdint.h>

#define VOCAB 32000
#define EMB   300
#define NFLT  100
#define HID   256
#define BB    32
#define TT    64
#define LL    48
#define NCOL  1200
#define BT    (BB*TT)

#define KTOT  960
#define NPAD  1280
#define MTILES 250
#define NTILES 10

// ---------------- device scratch ----------------
__device__ __align__(16) __half g_P[(size_t)VOCAB * NCOL];
__device__ __align__(16) __nv_bfloat16 g_A2[(size_t)VOCAB * KTOT];
__device__ __align__(16) __nv_bfloat16 g_B2[(size_t)NPAD * KTOT];
__device__ float g_rin[BT * 300];
__device__ float g_XG[2 * TT * 1024 * BB];
__device__ float g_HS[2 * TT * HID * BB];

__device__ __forceinline__ float sigf(float x) { return 1.0f / (1.0f + expf(-x)); }

__device__ __forceinline__ uint32_t smem_u32(const void* p) {
    uint32_t a;
    asm("{ .reg .u64 t; cvta.to.shared.u64 t, %1; cvt.u32.u64 %0, t; }" : "=r"(a) : "l"(p));
    return a;
}
#define CP_ASYNC16(d, s) asm volatile("cp.async.cg.shared.global [%0], [%1], 16;" :: "r"(d), "l"(s))
#define CP_COMMIT()      asm volatile("cp.async.commit_group;" ::: "memory")
#define CP_WAIT(n)       asm volatile("cp.async.wait_group %0;" :: "n"(n) : "memory")
#define LDMX4(r0, r1, r2, r3, addr) \
    asm volatile("ldmatrix.sync.aligned.m8n8.x4.shared.b16 {%0,%1,%2,%3}, [%4];" \
                 : "=r"(r0), "=r"(r1), "=r"(r2), "=r"(r3) : "r"(addr))
#define MMA16816(c, a, b) \
    asm volatile("mma.sync.aligned.m16n8k16.row.col.f32.bf16.bf16.f32 " \
                 "{%0,%1,%2,%3}, {%4,%5,%6,%7}, {%8,%9}, {%0,%1,%2,%3};" \
                 : "+f"((c)[0]), "+f"((c)[1]), "+f"((c)[2]), "+f"((c)[3]) \
                 : "r"((a)[0]), "r"((a)[1]), "r"((a)[2]), "r"((a)[3]), "r"((b)[0]), "r"((b)[1]))

#define CLUSTER_ARRIVE() asm volatile("barrier.cluster.arrive.aligned;" ::: "memory")
#define CLUSTER_WAIT()   asm volatile("barrier.cluster.wait.aligned;" ::: "memory")

__device__ __forceinline__ void dsmem_st_f32(uint32_t laddr, uint32_t rank, float v) {
    asm volatile(
        "{\n\t.reg .b32 ra;\n\t"
        "mapa.shared::cluster.u32 ra, %0, %1;\n\t"
        "st.shared::cluster.f32 [ra], %2;\n\t}"
        :: "r"(laddr), "r"(rank), "f"(v) : "memory");
}

// ---------------- build A2 = [Ahi | Ahi | Alo] ----------------
__global__ void convA_kernel(const float* __restrict__ emb) {
    int idx = blockIdx.x * blockDim.x + threadIdx.x;
    if (idx >= VOCAB * 160) return;
    int m  = idx / 160;
    int k2 = idx % 160;
    int k  = k2 * 2;
    float v0 = (k     < EMB) ? __ldg(&emb[(size_t)m * EMB + k])     : 0.0f;
    float v1 = (k + 1 < EMB) ? __ldg(&emb[(size_t)m * EMB + k + 1]) : 0.0f;
    __nv_bfloat16 h0 = __float2bfloat16(v0), h1 = __float2bfloat16(v1);
    __nv_bfloat16 l0 = __float2bfloat16(v0 - __bfloat162float(h0));
    __nv_bfloat16 l1 = __float2bfloat16(v1 - __bfloat162float(h1));
    uint32_t hp = (uint32_t)reinterpret_cast<unsigned short&>(h0) |
                  ((uint32_t)reinterpret_cast<unsigned short&>(h1) << 16);
    uint32_t lp = (uint32_t)reinterpret_cast<unsigned short&>(l0) |
                  ((uint32_t)reinterpret_cast<unsigned short&>(l1) << 16);
    uint32_t* A = (uint32_t*)g_A2;
    size_t base = (size_t)m * 480;
    A[base + k2]       = hp;
    A[base + 160 + k2] = hp;
    A[base + 320 + k2] = lp;
}

// ---------------- build B2 = [Bhi | Blo | Bhi] ----------------
__global__ void convB_kernel(const float* __restrict__ w3, const float* __restrict__ w4,
                             const float* __restrict__ w5) {
    int idx = blockIdx.x * blockDim.x + threadIdx.x;
    if (idx >= NPAD * 160) return;
    int n  = idx / 160;
    int k2 = idx % 160;
    int k0 = k2 * 2;
    float v0 = 0.0f, v1 = 0.0f;
    if (n < NCOL) {
        int c = n;
#pragma unroll
        for (int q = 0; q < 2; q++) {
            int k = k0 + q;
            float v = 0.0f;
            if (k < EMB) {
                if (c < 300)      { int fk = c / 100;        int nf = c % 100;        v = __ldg(&w3[((size_t)nf * EMB + k) * 3 + fk]); }
                else if (c < 700) { int c2 = c - 300; int fk = c2 / 100; int nf = c2 % 100; v = __ldg(&w4[((size_t)nf * EMB + k) * 4 + fk]); }
                else              { int c2 = c - 700; int fk = c2 / 100; int nf = c2 % 100; v = __ldg(&w5[((size_t)nf * EMB + k) * 5 + fk]); }
            }
            if (q == 0) v0 = v; else v1 = v;
        }
    }
    __nv_bfloat16 h0 = __float2bfloat16(v0), h1 = __float2bfloat16(v1);
    __nv_bfloat16 l0 = __float2bfloat16(v0 - __bfloat162float(h0));
    __nv_bfloat16 l1 = __float2bfloat16(v1 - __bfloat162float(h1));
    uint32_t hp = (uint32_t)reinterpret_cast<unsigned short&>(h0) |
                  ((uint32_t)reinterpret_cast<unsigned short&>(h1) << 16);
    uint32_t lp = (uint32_t)reinterpret_cast<unsigned short&>(l0) |
                  ((uint32_t)reinterpret_cast<unsigned short&>(l1) << 16);
    uint32_t* B = (uint32_t*)g_B2;
    size_t base = (size_t)n * 480;
    B[base + k2]       = hp;
    B[base + 160 + k2] = lp;
    B[base + 320 + k2] = hp;
}

// ---------------- HMMA GEMM (P) ----------------
__device__ __forceinline__ void load_chunk(uint32_t sAb, uint32_t sBb, int bm, int bn,
                                           int kk, int tid) {
    const uint8_t* Ab = (const uint8_t*)g_A2;
    const uint8_t* Bb = (const uint8_t*)g_B2;
#pragma unroll
    for (int i = 0; i < 4; i++) {
        int id = tid + i * 256;
        int r = id >> 3, c = id & 7;
        uint32_t d = sAb + r * 128 + ((c ^ (r & 7)) << 4);
        CP_ASYNC16(d, Ab + (size_t)(bm + r) * (KTOT * 2) + kk * 2 + c * 16);
    }
#pragma unroll
    for (int i = 0; i < 4; i++) {
        int id = tid + i * 256;
        int r = id >> 3, c = id & 7;
        uint32_t d = sBb + r * 128 + ((c ^ (r & 7)) << 4);
        CP_ASYNC16(d, Bb + (size_t)(bn + r) * (KTOT * 2) + kk * 2 + c * 16);
    }
}

__global__ void __launch_bounds__(256, 2) pgemm_mma_kernel() {
    extern __shared__ __align__(128) uint8_t dyn[];
    uint32_t sbase = smem_u32(dyn);
    int tid  = threadIdx.x;
    int wid  = tid >> 5, lane = tid & 31;
    int m0   = (wid & 1) * 64;
    int n0   = (wid >> 1) * 32;
    int bm   = blockIdx.y * 128;
    int bn   = blockIdx.x * 128;

    float acc[4][4][4];
#pragma unroll
    for (int i = 0; i < 4; i++)
#pragma unroll
        for (int j = 0; j < 4; j++)
#pragma unroll
            for (int q = 0; q < 4; q++) acc[i][j][q] = 0.0f;

    load_chunk(sbase, sbase + 16384, bm, bn, 0, tid);
    CP_COMMIT();

#pragma unroll 1
    for (int it = 0; it < 15; it++) {
        if (it < 14) {
            uint32_t nb = sbase + ((it + 1) & 1) * 32768;
            load_chunk(nb, nb + 16384, bm, bn, (it + 1) * 64, tid);
            CP_COMMIT();
            CP_WAIT(1);
        } else {
            CP_WAIT(0);
        }
        __syncthreads();

        uint32_t sAb = sbase + (it & 1) * 32768;
        uint32_t sBb = sAb + 16384;
#pragma unroll
        for (int ks = 0; ks < 4; ks++) {
            uint32_t a[4][4];
#pragma unroll
            for (int mf = 0; mf < 4; mf++) {
                int row = m0 + mf * 16 + (lane & 15);
                int ch  = ks * 2 + (lane >> 4);
                uint32_t addr = sAb + row * 128 + ((ch ^ (row & 7)) << 4);
                LDMX4(a[mf][0], a[mf][1], a[mf][2], a[mf][3], addr);
            }
            uint32_t b[4][2];
#pragma unroll
            for (int p = 0; p < 2; p++) {
                int sel = lane >> 3;
                int row = n0 + p * 16 + ((sel >> 1) << 3) + (lane & 7);
                int ch  = ks * 2 + (sel & 1);
                uint32_t addr = sBb + row * 128 + ((ch ^ (row & 7)) << 4);
                uint32_t r0, r1, r2, r3;
                LDMX4(r0, r1, r2, r3, addr);
                b[p * 2][0] = r0; b[p * 2][1] = r1;
                b[p * 2 + 1][0] = r2; b[p * 2 + 1][1] = r3;
            }
#pragma unroll
            for (int mf = 0; mf < 4; mf++)
#pragma unroll
                for (int nf = 0; nf < 4; nf++)
                    MMA16816(acc[mf][nf], a[mf], b[nf]);
        }
        __syncthreads();
    }

#pragma unroll
    for (int mf = 0; mf < 4; mf++) {
        int row0 = bm + m0 + mf * 16 + (lane >> 2);
#pragma unroll
        for (int nf = 0; nf < 4; nf++) {
            int col = bn + n0 + nf * 8 + 2 * (lane & 3);
            if (col < NCOL) {
                *(__half2*)(g_P + (size_t)row0 * NCOL + col) =
                    __floats2half2_rn(acc[mf][nf][0], acc[mf][nf][1]);
                *(__half2*)(g_P + (size_t)(row0 + 8) * NCOL + col) =
                    __floats2half2_rn(acc[mf][nf][2], acc[mf][nf][3]);
            }
        }
    }
}

// ---------------- conv gather (fp16 P, half2 per thread) ----------------
__global__ void conv_gather_kernel(const int* __restrict__ dia,
                                   const float* __restrict__ b3,
                                   const float* __restrict__ b4,
                                   const float* __restrict__ b5) {
    int bt = blockIdx.x;
    __shared__ int tok[LL];
    int tid = threadIdx.x;
    if (tid < LL) tok[tid] = dia[bt * LL + tid] * NCOL;
    __syncthreads();
    if (tid >= 50) return;
    int nf = tid * 2;
    const __half* P = g_P;

    float mx3 = -1e30f, my3 = -1e30f;
    for (int p = 0; p < 46; p++) {
        float2 a = __half22float2(*(const __half2*)(P + (size_t)tok[p]     + nf));
        float2 b = __half22float2(*(const __half2*)(P + (size_t)tok[p + 1] + 100 + nf));
        float2 c = __half22float2(*(const __half2*)(P + (size_t)tok[p + 2] + 200 + nf));
        mx3 = fmaxf(mx3, a.x + b.x + c.x);
        my3 = fmaxf(my3, a.y + b.y + c.y);
    }
    g_rin[bt * 300 + nf]     = fmaxf(mx3 + b3[nf], 0.0f);
    g_rin[bt * 300 + nf + 1] = fmaxf(my3 + b3[nf + 1], 0.0f);

    float mx4 = -1e30f, my4 = -1e30f;
    for (int p = 0; p < 45; p++) {
        float2 a = __half22float2(*(const __half2*)(P + (size_t)tok[p]     + 300 + nf));
        float2 b = __half22float2(*(const __half2*)(P + (size_t)tok[p + 1] + 400 + nf));
        float2 c = __half22float2(*(const __half2*)(P + (size_t)tok[p + 2] + 500 + nf));
        float2 d = __half22float2(*(const __half2*)(P + (size_t)tok[p + 3] + 600 + nf));
        mx4 = fmaxf(mx4, a.x + b.x + c.x + d.x);
        my4 = fmaxf(my4, a.y + b.y + c.y + d.y);
    }
    g_rin[bt * 300 + 100 + nf]     = fmaxf(mx4 + b4[nf], 0.0f);
    g_rin[bt * 300 + 100 + nf + 1] = fmaxf(my4 + b4[nf + 1], 0.0f);

    float mx5 = -1e30f, my5 = -1e30f;
    for (int p = 0; p < 44; p++) {
        float2 a = __half22float2(*(const __half2*)(P + (size_t)tok[p]     + 700 + nf));
        float2 b = __half22float2(*(const __half2*)(P + (size_t)tok[p + 1] + 800 + nf));
        float2 c = __half22float2(*(const __half2*)(P + (size_t)tok[p + 2] + 900 + nf));
        float2 d = __half22float2(*(const __half2*)(P + (size_t)tok[p + 3] + 1000 + nf));
        float2 e = __half22float2(*(const __half2*)(P + (size_t)tok[p + 4] + 1100 + nf));
        mx5 = fmaxf(mx5, a.x + b.x + c.x + d.x + e.x);
        my5 = fmaxf(my5, a.y + b.y + c.y + d.y + e.y);
    }
    g_rin[bt * 300 + 200 + nf]     = fmaxf(mx5 + b5[nf], 0.0f);
    g_rin[bt * 300 + 200 + nf + 1] = fmaxf(my5 + b5[nf + 1], 0.0f);
}

// ---------------- xg GEMM ----------------
__global__ void xg_gemm_kernel(const float* __restrict__ wih_f, const float* __restrict__ wih_r,
                               const float* __restrict__ bih_f, const float* __restrict__ bhh_f,
                               const float* __restrict__ bih_r, const float* __restrict__ bhh_r) {
    const int K = 300;
    __shared__ float sA[16][132];
    __shared__ float sB[16][68];
    int dir = blockIdx.z;
    const float* W  = dir ? wih_r : wih_f;
    const float* bi = dir ? bih_r : bih_f;
    const float* bh = dir ? bhh_r : bhh_f;
    int bm = blockIdx.y * 128;
    int bn = blockIdx.x * 64;
    int tid = threadIdx.x;
    int tx = tid & 15, ty = tid >> 4;
    float acc[8][4] = {};
    for (int kk = 0; kk < K; kk += 16) {
        int ak = tid & 15, am = tid >> 4;
        int gk = kk + ak;
#pragma unroll
        for (int i = 0; i < 8; i++) {
            int m  = am + i * 16;
            int gm = bm + m;
            int t  = gm >> 5, bb = gm & 31;
            int st = dir ? (63 - t) : t;
            sA[ak][m] = (gk < K) ? __ldg(&g_rin[(bb * 64 + st) * 300 + gk]) : 0.0f;
        }
        int wk = tid & 15, wn = tid >> 4;
#pragma unroll
        for (int i = 0; i < 4; i++) {
            int n   = wn + i * 16;
            int gkb = kk + wk;
            sB[wk][n] = (gkb < K) ? __ldg(&W[(bn + n) * 300 + gkb]) : 0.0f;
        }
        __syncthreads();
#pragma unroll
        for (int k = 0; k < 16; k++) {
            float4 a0 = *(const float4*)&sA[k][ty * 8];
            float4 a1 = *(const float4*)&sA[k][ty * 8 + 4];
            float4 b0 = *(const float4*)&sB[k][tx * 4];
            float ra[8] = {a0.x, a0.y, a0.z, a0.w, a1.x, a1.y, a1.z, a1.w};
            float rb[4] = {b0.x, b0.y, b0.z, b0.w};
#pragma unroll
            for (int i = 0; i < 8; i++)
#pragma unroll
                for (int j = 0; j < 4; j++) acc[i][j] += ra[i] * rb[j];
        }
        __syncthreads();
    }
#pragma unroll
    for (int i = 0; i < 8; i++) {
        int gm = bm + ty * 8 + i;
        int t = gm >> 5, bb = gm & 31;
#pragma unroll
        for (int j = 0; j < 4; j++) {
            int g = bn + tx * 4 + j;
            g_XG[(((size_t)dir * 64 + t) * 1024 + g) * 32 + bb] =
                acc[i][j] + __ldg(&bi[g]) + __ldg(&bh[g]);
        }
    }
}

// ================= HMMA cluster BiLSTM (R9 structure, proven) =================
#define LOFF_W    0
#define LOFF_HP   131072
#define LOFF_HS   147456          // 2 bufs x 16640 B (16 rows x 260 floats)
#define LOFF_RED  180736          // 8 KB
#define LOFF_SG   188928          // 16 x 132 floats = 8448 B
#define LSM_BYTES 197376

__device__ __forceinline__ uint32_t hp_off(int b, int k) {
    int chunk = k >> 6;
    int byte  = (k & 63) * 2;
    int c16   = byte >> 4;
    return (uint32_t)(LOFF_HP + chunk * 2048 + b * 128 + (((c16 ^ (b & 7)) << 4) | (byte & 15)));
}
__device__ __forceinline__ uint32_t w_off(int row, int chunk, int k) {
    int byte = k * 2;
    int c16  = byte >> 4;
    return (uint32_t)(LOFF_W + chunk * 16384 + row * 128 + (((c16 ^ (row & 7)) << 4) | (byte & 15)));
}

__global__ void __launch_bounds__(256, 1) __cluster_dims__(8, 1, 1)
lstm_mma_kernel(const float* __restrict__ whh_f, const float* __restrict__ whh_r) {
    extern __shared__ __align__(128) uint8_t lsm[];
    uint32_t sb = smem_u32(lsm);
    float* sRed = (float*)(lsm + LOFF_RED);
    float* sG   = (float*)(lsm + LOFF_SG);

    int tid = threadIdx.x;
    int w   = tid >> 5, lane = tid & 31;
    uint32_t rank;
    asm("mov.u32 %0, %%cluster_ctarank;" : "=r"(rank));
    int cid = blockIdx.x >> 3;
    int dir = cid >> 1;
    int bg  = cid & 1;
    int j0  = (int)rank * 32;
    const float* whh = dir ? whh_r : whh_f;
    const float* xg_glob = g_XG;

    for (int idx = tid; idx < 32768; idx += 256) {
        int row = idx >> 8;
        int k   = idx & 255;
        int jl = row >> 2, g = row & 3;
        float v = __ldg(&whh[(size_t)(g * 256 + j0 + jl) * 256 + k]);
        __nv_bfloat16 hi = __float2bfloat16(v);
        __nv_bfloat16 lo = __float2bfloat16(v - __bfloat162float(hi));
        *(__nv_bfloat16*)(lsm + w_off(row, k >> 6, k & 63))       = hi;
        *(__nv_bfloat16*)(lsm + w_off(row, (k >> 6) + 4, k & 63)) = lo;
    }
    for (int i = tid; i < 16384 / 4; i += 256) ((uint32_t*)(lsm + LOFF_HP))[i] = 0;
    for (int i = tid; i < 33280 / 4; i += 256) ((uint32_t*)(lsm + LOFF_HS))[i] = 0;
    __syncthreads();
    CLUSTER_ARRIVE();
    CLUSTER_WAIT();

    int nsl = w & 3;
    int kh  = w >> 2;
    int n0  = nsl * 32;

    int fjl[2], fb[2], fgj[2], fgb[2];
#pragma unroll
    for (int pp = 0; pp < 2; pp++) {
        int p = tid + pp * 256;
        fjl[pp] = p >> 4;
        fb[pp]  = p & 15;
        fgj[pp] = j0 + fjl[pp];
        fgb[pp] = bg * 16 + fb[pp];
    }
    float cst[2] = {0.0f, 0.0f};

    const int passW[3] = {0, 0, 4};
    const int passH[3] = {0, 4, 0};

    for (int s = 0; s < 64; s++) {
        float xai[2], xaf[2], xag[2], xao[2];
        {
            size_t xbase = (((size_t)dir * 64 + s) * 1024) * 32;
#pragma unroll
            for (int pp = 0; pp < 2; pp++) {
                xai[pp] = __ldg(&xg_glob[xbase + (size_t)(0   + fgj[pp]) * 32 + fgb[pp]]);
                xaf[pp] = __ldg(&xg_glob[xbase + (size_t)(256 + fgj[pp]) * 32 + fgb[pp]]);
                xag[pp] = __ldg(&xg_glob[xbase + (size_t)(512 + fgj[pp]) * 32 + fgb[pp]]);
                xao[pp] = __ldg(&xg_glob[xbase + (size_t)(768 + fgj[pp]) * 32 + fgb[pp]]);
            }
        }

        float acc[4][4];
#pragma unroll
        for (int nf = 0; nf < 4; nf++)
#pragma unroll
            for (int q = 0; q < 4; q++) acc[nf][q] = 0.0f;

#pragma unroll
        for (int ps = 0; ps < 3; ps++) {
            int wb = passW[ps] + kh * 2;
            int hb = passH[ps] + kh * 2;
#pragma unroll
            for (int cc = 0; cc < 2; cc++) {
                uint32_t wbase = sb + LOFF_W + (wb + cc) * 16384;
                uint32_t hbase = sb + LOFF_HP + (hb + cc) * 2048;
#pragma unroll
                for (int ks = 0; ks < 4; ks++) {
                    uint32_t a[4];
                    {
                        int row = lane & 15;
                        int ch  = ks * 2 + (lane >> 4);
                        uint32_t addr = hbase + row * 128 + ((ch ^ (row & 7)) << 4);
                        LDMX4(a[0], a[1], a[2], a[3], addr);
                    }
                    uint32_t b[4][2];
#pragma unroll
                    for (int p = 0; p < 2; p++) {
                        int sel = lane >> 3;
                        int row = n0 + p * 16 + ((sel >> 1) << 3) + (lane & 7);
                        int ch  = ks * 2 + (sel & 1);
                        uint32_t addr = wbase + row * 128 + ((ch ^ (row & 7)) << 4);
                        uint32_t r0, r1, r2, r3;
                        LDMX4(r0, r1, r2, r3, addr);
                        b[p * 2][0] = r0; b[p * 2][1] = r1;
                        b[p * 2 + 1][0] = r2; b[p * 2 + 1][1] = r3;
                    }
#pragma unroll
                    for (int nf = 0; nf < 4; nf++)
                        MMA16816(acc[nf], a, b[nf]);
                }
            }
        }

        if (kh == 1) {
            float* rp = sRed + (nsl * 32 + lane) * 16;
#pragma unroll
            for (int nf = 0; nf < 4; nf++)
                *(float4*)(rp + nf * 4) = make_float4(acc[nf][0], acc[nf][1], acc[nf][2], acc[nf][3]);
        }
        __syncthreads();
        if (kh == 0) {
            const float* rp = sRed + (nsl * 32 + lane) * 16;
            int row = lane >> 2;
            int colb = n0 + 2 * (lane & 3);
#pragma unroll
            for (int nf = 0; nf < 4; nf++) {
                int col = colb + nf * 8;
                sG[row * 132 + col]           = acc[nf][0] + rp[nf * 4 + 0];
                sG[row * 132 + col + 1]       = acc[nf][1] + rp[nf * 4 + 1];
                sG[(row + 8) * 132 + col]     = acc[nf][2] + rp[nf * 4 + 2];
                sG[(row + 8) * 132 + col + 1] = acc[nf][3] + rp[nf * 4 + 3];
            }
        }
        __syncthreads();

        int wbuf = s & 1;
        uint32_t hsbase = sb + LOFF_HS + wbuf * 16640;
#pragma unroll
        for (int pp = 0; pp < 2; pp++) {
            const float* gr = sG + fb[pp] * 132 + fjl[pp] * 4;
            float ai = gr[0] + xai[pp];
            float af = gr[1] + xaf[pp];
            float ag = gr[2] + xag[pp];
            float ao = gr[3] + xao[pp];

            float iv = sigf(ai), fv = sigf(af), gv = tanhf(ag), ov = sigf(ao);
            cst[pp] = fv * cst[pp] + iv * gv;
            float h = ov * tanhf(cst[pp]);

            uint32_t laddr = hsbase + (uint32_t)(fb[pp] * 260 + fgj[pp]) * 4u;
#pragma unroll
            for (uint32_t tr = 0; tr < 8; tr++) dsmem_st_f32(laddr, tr, h);

            int tout = dir ? (63 - s) : s;
            g_HS[(((size_t)dir * 64 + tout) * HID + fgj[pp]) * 32 + fgb[pp]] = h;
        }

        CLUSTER_ARRIVE();
        CLUSTER_WAIT();

        if (s < 63) {
            const float* hs = (const float*)(lsm + LOFF_HS + wbuf * 16640);
#pragma unroll
            for (int q = 0; q < 16; q++) {
                float v = hs[q * 260 + tid];
                __nv_bfloat16 hi = __float2bfloat16(v);
                __nv_bfloat16 lo = __float2bfloat16(v - __bfloat162float(hi));
                *(__nv_bfloat16*)(lsm + hp_off(q, tid))       = hi;
                *(__nv_bfloat16*)(lsm + hp_off(q, 256 + tid)) = lo;
            }
            __syncthreads();
        }
    }
}

// ---------------- head ----------------
__global__ void head_kernel(const float* __restrict__ hw, const float* __restrict__ hb,
                            float* __restrict__ out) {
    int t = blockIdx.x;
    int tid = threadIdx.x;
    int b  = tid & 31;
    int og = tid >> 5;
    const float* hf = g_HS + (size_t)(t * HID) * 32;
    const float* hr = g_HS + (size_t)((64 + t) * HID) * 32;
    float a0 = 0.f, a1 = 0.f, a2 = 0.f, a3 = 0.f;
    int o = og * 4;
    for (int h = 0; h < HID; h++) {
        float vf = __ldg(&hf[h * 32 + b]);
        float vr = __ldg(&hr[h * 32 + b]);
        a0 += vf * __ldg(&hw[(o + 0) * 512 + h]) + vr * __ldg(&hw[(o + 0) * 512 + 256 + h]);
        a1 += vf * __ldg(&hw[(o + 1) * 512 + h]) + vr * __ldg(&hw[(o + 1) * 512 + 256 + h]);
        a2 += vf * __ldg(&hw[(o + 2) * 512 + h]) + vr * __ldg(&hw[(o + 2) * 512 + 256 + h]);
        a3 += vf * __ldg(&hw[(o + 3) * 512 + h]) + vr * __ldg(&hw[(o + 3) * 512 + 256 + h]);
    }
    size_t base = ((size_t)b * 64 + t) * 32 + o;
    out[base + 0] = sigf(a0 + __ldg(&hb[o + 0]));
    out[base + 1] = sigf(a1 + __ldg(&hb[o + 1]));
    out[base + 2] = sigf(a2 + __ldg(&hb[o + 2]));
    out[base + 3] = sigf(a3 + __ldg(&hb[o + 3]));
}

// ---------------- launch ----------------
extern "C" void kernel_launch(void* const* d_in, const int* in_sizes, int n_in,
                              void* d_out, int out_size) {
    const int*   dialogue = (const int*)d_in[0];
    const float* emb   = (const float*)d_in[1];
    const float* w3    = (const float*)d_in[2];
    const float* b3    = (const float*)d_in[3];
    const float* w4    = (const float*)d_in[4];
    const float* b4    = (const float*)d_in[5];
    const float* w5    = (const float*)d_in[6];
    const float* b5    = (const float*)d_in[7];
    const float* wih_f = (const float*)d_in[8];
    const float* whh_f = (const float*)d_in[9];
    const float* bih_f = (const float*)d_in[10];
    const float* bhh_f = (const float*)d_in[11];
    const float* wih_r = (const float*)d_in[12];
    const float* whh_r = (const float*)d_in[13];
    const float* bih_r = (const float*)d_in[14];
    const float* bhh_r = (const float*)d_in[15];
    const float* hw    = (const float*)d_in[16];
    const float* hb    = (const float*)d_in[17];
    float* out = (float*)d_out;

    cudaFuncSetAttribute(pgemm_mma_kernel, cudaFuncAttributeMaxDynamicSharedMemorySize, 65536);
    cudaFuncSetAttribute(lstm_mma_kernel, cudaFuncAttributeMaxDynamicSharedMemorySize, LSM_BYTES);

    convA_kernel<<<(VOCAB * 160 + 255) / 256, 256>>>(emb);
    convB_kernel<<<(NPAD * 160 + 255) / 256, 256>>>(w3, w4, w5);

    dim3 gP(NTILES, MTILES);
    pgemm_mma_kernel<<<gP, 256, 65536>>>();

    conv_gather_kernel<<<BT, 64>>>(dialogue, b3, b4, b5);

    dim3 gX(16, 16, 2);
    xg_gemm_kernel<<<gX, 256>>>(wih_f, wih_r, bih_f, bhh_f, bih_r, bhh_r);

    lstm_mma_kernel<<<32, 256, LSM_BYTES>>>(whh_f, whh_r);

    head_kernel<<<TT, 256>>>(hw, hb, out);
}

// round 16
// speedup vs baseline: 1.2607x; 1.1421x over previous
#include <cuda_runtime.h>
#include <cuda_bf16.h>
#include <cuda_fp16.h>
#include <math.h>
#include <stdint.h>

#define VOCAB 32000
#define EMB   300
#define NFLT  100
#define HID   256
#define BB    32
#define TT    64
#define LL    48
#define NCOL  1200
#define BT    (BB*TT)

#define KTOT  960
#define NPAD  1280
#define MTILES 250
#define NTILES 10

// ---------------- device scratch ----------------
__device__ __align__(16) __half g_P[(size_t)VOCAB * NCOL];
__device__ __align__(16) __nv_bfloat16 g_A2[(size_t)VOCAB * KTOT];
__device__ __align__(16) __nv_bfloat16 g_B2[(size_t)NPAD * KTOT];
__device__ float g_rin[BT * 300];
__device__ float g_XG[2 * TT * 1024 * BB];
__device__ float g_HS[2 * TT * HID * BB];

__device__ __forceinline__ float sigf(float x) { return 1.0f / (1.0f + expf(-x)); }

__device__ __forceinline__ uint32_t smem_u32(const void* p) {
    uint32_t a;
    asm("{ .reg .u64 t; cvta.to.shared.u64 t, %1; cvt.u32.u64 %0, t; }" : "=r"(a) : "l"(p));
    return a;
}
#define CP_ASYNC16(d, s) asm volatile("cp.async.cg.shared.global [%0], [%1], 16;" :: "r"(d), "l"(s))
#define CP_COMMIT()      asm volatile("cp.async.commit_group;" ::: "memory")
#define CP_WAIT(n)       asm volatile("cp.async.wait_group %0;" :: "n"(n) : "memory")
#define LDMX4(r0, r1, r2, r3, addr) \
    asm volatile("ldmatrix.sync.aligned.m8n8.x4.shared.b16 {%0,%1,%2,%3}, [%4];" \
                 : "=r"(r0), "=r"(r1), "=r"(r2), "=r"(r3) : "r"(addr))
#define MMA16816(c, a, b) \
    asm volatile("mma.sync.aligned.m16n8k16.row.col.f32.bf16.bf16.f32 " \
                 "{%0,%1,%2,%3}, {%4,%5,%6,%7}, {%8,%9}, {%0,%1,%2,%3};" \
                 : "+f"((c)[0]), "+f"((c)[1]), "+f"((c)[2]), "+f"((c)[3]) \
                 : "r"((a)[0]), "r"((a)[1]), "r"((a)[2]), "r"((a)[3]), "r"((b)[0]), "r"((b)[1]))
#define MMA16816H(c, a, b) \
    asm volatile("mma.sync.aligned.m16n8k16.row.col.f32.f16.f16.f32 " \
                 "{%0,%1,%2,%3}, {%4,%5,%6,%7}, {%8,%9}, {%0,%1,%2,%3};" \
                 : "+f"((c)[0]), "+f"((c)[1]), "+f"((c)[2]), "+f"((c)[3]) \
                 : "r"((a)[0]), "r"((a)[1]), "r"((a)[2]), "r"((a)[3]), "r"((b)[0]), "r"((b)[1]))

#define CLUSTER_ARRIVE() asm volatile("barrier.cluster.arrive.aligned;" ::: "memory")
#define CLUSTER_WAIT()   asm volatile("barrier.cluster.wait.aligned;" ::: "memory")

__device__ __forceinline__ void dsmem_st_b64(uint32_t laddr, uint32_t rank, unsigned long long v) {
    asm volatile(
        "{\n\t.reg .b32 ra;\n\t"
        "mapa.shared::cluster.u32 ra, %0, %1;\n\t"
        "st.shared::cluster.b64 [ra], %2;\n\t}"
        :: "r"(laddr), "r"(rank), "l"(v) : "memory");
}

// ---------------- build A2 = [Ahi | Ahi | Alo] ----------------
__global__ void convA_kernel(const float* __restrict__ emb) {
    int idx = blockIdx.x * blockDim.x + threadIdx.x;
    if (idx >= VOCAB * 160) return;
    int m  = idx / 160;
    int k2 = idx % 160;
    int k  = k2 * 2;
    float v0 = (k     < EMB) ? __ldg(&emb[(size_t)m * EMB + k])     : 0.0f;
    float v1 = (k + 1 < EMB) ? __ldg(&emb[(size_t)m * EMB + k + 1]) : 0.0f;
    __nv_bfloat16 h0 = __float2bfloat16(v0), h1 = __float2bfloat16(v1);
    __nv_bfloat16 l0 = __float2bfloat16(v0 - __bfloat162float(h0));
    __nv_bfloat16 l1 = __float2bfloat16(v1 - __bfloat162float(h1));
    uint32_t hp = (uint32_t)reinterpret_cast<unsigned short&>(h0) |
                  ((uint32_t)reinterpret_cast<unsigned short&>(h1) << 16);
    uint32_t lp = (uint32_t)reinterpret_cast<unsigned short&>(l0) |
                  ((uint32_t)reinterpret_cast<unsigned short&>(l1) << 16);
    uint32_t* A = (uint32_t*)g_A2;
    size_t base = (size_t)m * 480;
    A[base + k2]       = hp;
    A[base + 160 + k2] = hp;
    A[base + 320 + k2] = lp;
}

// ---------------- build B2 = [Bhi | Blo | Bhi] ----------------
__global__ void convB_kernel(const float* __restrict__ w3, const float* __restrict__ w4,
                             const float* __restrict__ w5) {
    int idx = blockIdx.x * blockDim.x + threadIdx.x;
    if (idx >= NPAD * 160) return;
    int n  = idx / 160;
    int k2 = idx % 160;
    int k0 = k2 * 2;
    float v0 = 0.0f, v1 = 0.0f;
    if (n < NCOL) {
        int c = n;
#pragma unroll
        for (int q = 0; q < 2; q++) {
            int k = k0 + q;
            float v = 0.0f;
            if (k < EMB) {
                if (c < 300)      { int fk = c / 100;        int nf = c % 100;        v = __ldg(&w3[((size_t)nf * EMB + k) * 3 + fk]); }
                else if (c < 700) { int c2 = c - 300; int fk = c2 / 100; int nf = c2 % 100; v = __ldg(&w4[((size_t)nf * EMB + k) * 4 + fk]); }
                else              { int c2 = c - 700; int fk = c2 / 100; int nf = c2 % 100; v = __ldg(&w5[((size_t)nf * EMB + k) * 5 + fk]); }
            }
            if (q == 0) v0 = v; else v1 = v;
        }
    }
    __nv_bfloat16 h0 = __float2bfloat16(v0), h1 = __float2bfloat16(v1);
    __nv_bfloat16 l0 = __float2bfloat16(v0 - __bfloat162float(h0));
    __nv_bfloat16 l1 = __float2bfloat16(v1 - __bfloat162float(h1));
    uint32_t hp = (uint32_t)reinterpret_cast<unsigned short&>(h0) |
                  ((uint32_t)reinterpret_cast<unsigned short&>(h1) << 16);
    uint32_t lp = (uint32_t)reinterpret_cast<unsigned short&>(l0) |
                  ((uint32_t)reinterpret_cast<unsigned short&>(l1) << 16);
    uint32_t* B = (uint32_t*)g_B2;
    size_t base = (size_t)n * 480;
    B[base + k2]       = hp;
    B[base + 160 + k2] = lp;
    B[base + 320 + k2] = hp;
}

// ---------------- HMMA GEMM (P) ----------------
__device__ __forceinline__ void load_chunk(uint32_t sAb, uint32_t sBb, int bm, int bn,
                                           int kk, int tid) {
    const uint8_t* Ab = (const uint8_t*)g_A2;
    const uint8_t* Bb = (const uint8_t*)g_B2;
#pragma unroll
    for (int i = 0; i < 4; i++) {
        int id = tid + i * 256;
        int r = id >> 3, c = id & 7;
        uint32_t d = sAb + r * 128 + ((c ^ (r & 7)) << 4);
        CP_ASYNC16(d, Ab + (size_t)(bm + r) * (KTOT * 2) + kk * 2 + c * 16);
    }
#pragma unroll
    for (int i = 0; i < 4; i++) {
        int id = tid + i * 256;
        int r = id >> 3, c = id & 7;
        uint32_t d = sBb + r * 128 + ((c ^ (r & 7)) << 4);
        CP_ASYNC16(d, Bb + (size_t)(bn + r) * (KTOT * 2) + kk * 2 + c * 16);
    }
}

__global__ void __launch_bounds__(256, 2) pgemm_mma_kernel() {
    extern __shared__ __align__(128) uint8_t dyn[];
    uint32_t sbase = smem_u32(dyn);
    int tid  = threadIdx.x;
    int wid  = tid >> 5, lane = tid & 31;
    int m0   = (wid & 1) * 64;
    int n0   = (wid >> 1) * 32;
    int bm   = blockIdx.y * 128;
    int bn   = blockIdx.x * 128;

    float acc[4][4][4];
#pragma unroll
    for (int i = 0; i < 4; i++)
#pragma unroll
        for (int j = 0; j < 4; j++)
#pragma unroll
            for (int q = 0; q < 4; q++) acc[i][j][q] = 0.0f;

    load_chunk(sbase, sbase + 16384, bm, bn, 0, tid);
    CP_COMMIT();

#pragma unroll 1
    for (int it = 0; it < 15; it++) {
        if (it < 14) {
            uint32_t nb = sbase + ((it + 1) & 1) * 32768;
            load_chunk(nb, nb + 16384, bm, bn, (it + 1) * 64, tid);
            CP_COMMIT();
            CP_WAIT(1);
        } else {
            CP_WAIT(0);
        }
        __syncthreads();

        uint32_t sAb = sbase + (it & 1) * 32768;
        uint32_t sBb = sAb + 16384;
#pragma unroll
        for (int ks = 0; ks < 4; ks++) {
            uint32_t a[4][4];
#pragma unroll
            for (int mf = 0; mf < 4; mf++) {
                int row = m0 + mf * 16 + (lane & 15);
                int ch  = ks * 2 + (lane >> 4);
                uint32_t addr = sAb + row * 128 + ((ch ^ (row & 7)) << 4);
                LDMX4(a[mf][0], a[mf][1], a[mf][2], a[mf][3], addr);
            }
            uint32_t b[4][2];
#pragma unroll
            for (int p = 0; p < 2; p++) {
                int sel = lane >> 3;
                int row = n0 + p * 16 + ((sel >> 1) << 3) + (lane & 7);
                int ch  = ks * 2 + (sel & 1);
                uint32_t addr = sBb + row * 128 + ((ch ^ (row & 7)) << 4);
                uint32_t r0, r1, r2, r3;
                LDMX4(r0, r1, r2, r3, addr);
                b[p * 2][0] = r0; b[p * 2][1] = r1;
                b[p * 2 + 1][0] = r2; b[p * 2 + 1][1] = r3;
            }
#pragma unroll
            for (int mf = 0; mf < 4; mf++)
#pragma unroll
                for (int nf = 0; nf < 4; nf++)
                    MMA16816(acc[mf][nf], a[mf], b[nf]);
        }
        __syncthreads();
    }

#pragma unroll
    for (int mf = 0; mf < 4; mf++) {
        int row0 = bm + m0 + mf * 16 + (lane >> 2);
#pragma unroll
        for (int nf = 0; nf < 4; nf++) {
            int col = bn + n0 + nf * 8 + 2 * (lane & 3);
            if (col < NCOL) {
                *(__half2*)(g_P + (size_t)row0 * NCOL + col) =
                    __floats2half2_rn(acc[mf][nf][0], acc[mf][nf][1]);
                *(__half2*)(g_P + (size_t)(row0 + 8) * NCOL + col) =
                    __floats2half2_rn(acc[mf][nf][2], acc[mf][nf][3]);
            }
        }
    }
}

// ---------------- conv gather (fp16 P, half2 per thread) ----------------
__global__ void conv_gather_kernel(const int* __restrict__ dia,
                                   const float* __restrict__ b3,
                                   const float* __restrict__ b4,
                                   const float* __restrict__ b5) {
    int bt = blockIdx.x;
    __shared__ int tok[LL];
    int tid = threadIdx.x;
    if (tid < LL) tok[tid] = dia[bt * LL + tid] * NCOL;
    __syncthreads();
    if (tid >= 50) return;
    int nf = tid * 2;
    const __half* P = g_P;

    float mx3 = -1e30f, my3 = -1e30f;
    for (int p = 0; p < 46; p++) {
        float2 a = __half22float2(*(const __half2*)(P + (size_t)tok[p]     + nf));
        float2 b = __half22float2(*(const __half2*)(P + (size_t)tok[p + 1] + 100 + nf));
        float2 c = __half22float2(*(const __half2*)(P + (size_t)tok[p + 2] + 200 + nf));
        mx3 = fmaxf(mx3, a.x + b.x + c.x);
        my3 = fmaxf(my3, a.y + b.y + c.y);
    }
    g_rin[bt * 300 + nf]     = fmaxf(mx3 + b3[nf], 0.0f);
    g_rin[bt * 300 + nf + 1] = fmaxf(my3 + b3[nf + 1], 0.0f);

    float mx4 = -1e30f, my4 = -1e30f;
    for (int p = 0; p < 45; p++) {
        float2 a = __half22float2(*(const __half2*)(P + (size_t)tok[p]     + 300 + nf));
        float2 b = __half22float2(*(const __half2*)(P + (size_t)tok[p + 1] + 400 + nf));
        float2 c = __half22float2(*(const __half2*)(P + (size_t)tok[p + 2] + 500 + nf));
        float2 d = __half22float2(*(const __half2*)(P + (size_t)tok[p + 3] + 600 + nf));
        mx4 = fmaxf(mx4, a.x + b.x + c.x + d.x);
        my4 = fmaxf(my4, a.y + b.y + c.y + d.y);
    }
    g_rin[bt * 300 + 100 + nf]     = fmaxf(mx4 + b4[nf], 0.0f);
    g_rin[bt * 300 + 100 + nf + 1] = fmaxf(my4 + b4[nf + 1], 0.0f);

    float mx5 = -1e30f, my5 = -1e30f;
    for (int p = 0; p < 44; p++) {
        float2 a = __half22float2(*(const __half2*)(P + (size_t)tok[p]     + 700 + nf));
        float2 b = __half22float2(*(const __half2*)(P + (size_t)tok[p + 1] + 800 + nf));
        float2 c = __half22float2(*(const __half2*)(P + (size_t)tok[p + 2] + 900 + nf));
        float2 d = __half22float2(*(const __half2*)(P + (size_t)tok[p + 3] + 1000 + nf));
        float2 e = __half22float2(*(const __half2*)(P + (size_t)tok[p + 4] + 1100 + nf));
        mx5 = fmaxf(mx5, a.x + b.x + c.x + d.x + e.x);
        my5 = fmaxf(my5, a.y + b.y + c.y + d.y + e.y);
    }
    g_rin[bt * 300 + 200 + nf]     = fmaxf(mx5 + b5[nf], 0.0f);
    g_rin[bt * 300 + 200 + nf + 1] = fmaxf(my5 + b5[nf + 1], 0.0f);
}

// ---------------- xg GEMM ----------------
__global__ void xg_gemm_kernel(const float* __restrict__ wih_f, const float* __restrict__ wih_r,
                               const float* __restrict__ bih_f, const float* __restrict__ bhh_f,
                               const float* __restrict__ bih_r, const float* __restrict__ bhh_r) {
    const int K = 300;
    __shared__ float sA[16][132];
    __shared__ float sB[16][68];
    int dir = blockIdx.z;
    const float* W  = dir ? wih_r : wih_f;
    const float* bi = dir ? bih_r : bih_f;
    const float* bh = dir ? bhh_r : bhh_f;
    int bm = blockIdx.y * 128;
    int bn = blockIdx.x * 64;
    int tid = threadIdx.x;
    int tx = tid & 15, ty = tid >> 4;
    float acc[8][4] = {};
    for (int kk = 0; kk < K; kk += 16) {
        int ak = tid & 15, am = tid >> 4;
        int gk = kk + ak;
#pragma unroll
        for (int i = 0; i < 8; i++) {
            int m  = am + i * 16;
            int gm = bm + m;
            int t  = gm >> 5, bb = gm & 31;
            int st = dir ? (63 - t) : t;
            sA[ak][m] = (gk < K) ? __ldg(&g_rin[(bb * 64 + st) * 300 + gk]) : 0.0f;
        }
        int wk = tid & 15, wn = tid >> 4;
#pragma unroll
        for (int i = 0; i < 4; i++) {
            int n   = wn + i * 16;
            int gkb = kk + wk;
            sB[wk][n] = (gkb < K) ? __ldg(&W[(bn + n) * 300 + gkb]) : 0.0f;
        }
        __syncthreads();
#pragma unroll
        for (int k = 0; k < 16; k++) {
            float4 a0 = *(const float4*)&sA[k][ty * 8];
            float4 a1 = *(const float4*)&sA[k][ty * 8 + 4];
            float4 b0 = *(const float4*)&sB[k][tx * 4];
            float ra[8] = {a0.x, a0.y, a0.z, a0.w, a1.x, a1.y, a1.z, a1.w};
            float rb[4] = {b0.x, b0.y, b0.z, b0.w};
#pragma unroll
            for (int i = 0; i < 8; i++)
#pragma unroll
                for (int j = 0; j < 4; j++) acc[i][j] += ra[i] * rb[j];
        }
        __syncthreads();
    }
#pragma unroll
    for (int i = 0; i < 8; i++) {
        int gm = bm + ty * 8 + i;
        int t = gm >> 5, bb = gm & 31;
#pragma unroll
        for (int j = 0; j < 4; j++) {
            int g = bn + tx * 4 + j;
            g_XG[(((size_t)dir * 64 + t) * 1024 + g) * 32 + bb] =
                acc[i][j] + __ldg(&bi[g]) + __ldg(&bh[g]);
        }
    }
}

// ================= fp16 HMMA cluster BiLSTM v4 =================
// 4 clusters (dir x batch-half16) x 4 CTAs (rank = 64 j -> 256 gate-rows)
// Single fp16 W and h (fp32 accum): K=256, no k-split, no reconvert phase.
// W: 256 rows x 256 k fp16 = 128KB. h' tile: 16 b x 256 k fp16, double buffered.
// Finalists write fp16 h directly to all 4 ranks via packed b64 remote stores.
#define LOFF_W    0                  // 4 chunks x 32768 B = 131072
#define LOFF_HP   131072             // 2 bufs x 8192 B
#define LOFF_SG   147456             // 16 x 264 floats = 16896 B
#define LSM_BYTES 164352

__device__ __forceinline__ uint32_t w_off16(int row, int chunk, int k) {   // k 0..63
    int byte = k * 2;
    int c16  = byte >> 4;
    return (uint32_t)(LOFF_W + chunk * 32768 + row * 128 + (((c16 ^ (row & 7)) << 4) | (byte & 15)));
}

__global__ void __launch_bounds__(256, 1) __cluster_dims__(4, 1, 1)
lstm_mma_kernel(const float* __restrict__ whh_f, const float* __restrict__ whh_r) {
    extern __shared__ __align__(128) uint8_t lsm[];
    uint32_t sb = smem_u32(lsm);
    float* sG = (float*)(lsm + LOFF_SG);

    int tid = threadIdx.x;
    int w   = tid >> 5, lane = tid & 31;
    uint32_t rank;
    asm("mov.u32 %0, %%cluster_ctarank;" : "=r"(rank));
    int cid = blockIdx.x >> 2;
    int dir = cid >> 1;
    int bg  = cid & 1;                 // batch half (16)
    int j0  = (int)rank * 64;          // this CTA's 64 hidden units
    const float* whh = dir ? whh_r : whh_f;
    const float* xg_glob = g_XG;

    // ---- load W slice (once): 256 rows (jl*4+g) x 256 k, fp16, swizzled ----
    for (int idx = tid; idx < 65536; idx += 256) {
        int row = idx >> 8;            // 0..255
        int k   = idx & 255;
        int jl = row >> 2, g = row & 3;
        float v = __ldg(&whh[(size_t)(g * 256 + j0 + jl) * 256 + k]);
        *(__half*)(lsm + w_off16(row, k >> 6, k & 63)) = __float2half(v);
    }
    // zero both h' buffers (16 KB)
    for (int i = tid; i < 16384 / 4; i += 256) ((uint32_t*)(lsm + LOFF_HP))[i] = 0;
    __syncthreads();
    CLUSTER_ARRIVE();
    CLUSTER_WAIT();

    int n0 = w * 32;                   // this warp's 32 gate-rows

    // finalist mapping: thread owns b = tid&15, jlg = tid>>4; cells jl = jlg*4+pp
    int fb  = tid & 15;
    int jlg = tid >> 4;
    int gb  = bg * 16 + fb;
    float cst[4] = {0.0f, 0.0f, 0.0f, 0.0f};

    // precomputed remote-store address component (chunk == rank by construction)
    int byte0 = jlg * 8;               // (k0 & 63) * 2, k0 = j0 + jlg*4
    uint32_t hp_st_off = (uint32_t)(LOFF_HP + (int)rank * 2048 + fb * 128 +
                                    ((((byte0 >> 4) ^ (fb & 7)) << 4) | (byte0 & 15)));

    for (int s = 0; s < 64; s++) {
        int rbuf = s & 1;
        int wbuf = rbuf ^ 1;

        // ---- phase 0: prefetch XG (16 values; overlaps MMA) ----
        float xg[4][4];
        {
            size_t xbase = (((size_t)dir * 64 + s) * 1024) * 32;
#pragma unroll
            for (int pp = 0; pp < 4; pp++) {
                int gj = j0 + jlg * 4 + pp;
#pragma unroll
                for (int g = 0; g < 4; g++)
                    xg[pp][g] = __ldg(&xg_glob[xbase + (size_t)(g * 256 + gj) * 32 + gb]);
            }
        }

        // ---- phase 1: fp16 HMMA, 32 gate-rows x M=16 x K=256 ----
        float acc[4][4];
#pragma unroll
        for (int nf = 0; nf < 4; nf++)
#pragma unroll
            for (int q = 0; q < 4; q++) acc[nf][q] = 0.0f;

#pragma unroll
        for (int cc = 0; cc < 4; cc++) {
            uint32_t wbase = sb + LOFF_W + cc * 32768;
            uint32_t hbase = sb + LOFF_HP + rbuf * 8192 + cc * 2048;
#pragma unroll
            for (int ks = 0; ks < 4; ks++) {
                uint32_t a[4];
                {
                    int row = lane & 15;
                    int ch  = ks * 2 + (lane >> 4);
                    uint32_t addr = hbase + row * 128 + ((ch ^ (row & 7)) << 4);
                    LDMX4(a[0], a[1], a[2], a[3], addr);
                }
                uint32_t b[4][2];
#pragma unroll
                for (int p = 0; p < 2; p++) {
                    int sel = lane >> 3;
                    int row = n0 + p * 16 + ((sel >> 1) << 3) + (lane & 7);
                    int ch  = ks * 2 + (sel & 1);
                    uint32_t addr = wbase + row * 128 + ((ch ^ (row & 7)) << 4);
                    uint32_t r0, r1, r2, r3;
                    LDMX4(r0, r1, r2, r3, addr);
                    b[p * 2][0] = r0; b[p * 2][1] = r1;
                    b[p * 2 + 1][0] = r2; b[p * 2 + 1][1] = r3;
                }
#pragma unroll
                for (int nf = 0; nf < 4; nf++)
                    MMA16816H(acc[nf], a, b[nf]);
            }
        }

        // ---- phase 2: write gate buffer sG[b 16][264] ----
        {
            int rowb = lane >> 2;
            int colb = n0 + 2 * (lane & 3);
#pragma unroll
            for (int nf = 0; nf < 4; nf++) {
                int col = colb + nf * 8;
                sG[rowb * 264 + col]           = acc[nf][0];
                sG[rowb * 264 + col + 1]       = acc[nf][1];
                sG[(rowb + 8) * 264 + col]     = acc[nf][2];
                sG[(rowb + 8) * 264 + col + 1] = acc[nf][3];
            }
        }
        __syncthreads();

        // ---- phase 3: gates + cell update (4 cells/thread), packed b64 remote store ----
        {
            __half hh[4];
            int tout = dir ? (63 - s) : s;
#pragma unroll
            for (int pp = 0; pp < 4; pp++) {
                int jl = jlg * 4 + pp;
                const float* gr = sG + fb * 264 + jl * 4;
                float ai = gr[0] + xg[pp][0];
                float af = gr[1] + xg[pp][1];
                float ag = gr[2] + xg[pp][2];
                float ao = gr[3] + xg[pp][3];
                float iv = sigf(ai), fv = sigf(af), gv = tanhf(ag), ov = sigf(ao);
                cst[pp] = fv * cst[pp] + iv * gv;
                float h = ov * tanhf(cst[pp]);
                hh[pp] = __float2half(h);
                g_HS[(((size_t)dir * 64 + tout) * HID + (j0 + jl)) * 32 + gb] = h;
            }
            unsigned long long pk =
                (unsigned long long)reinterpret_cast<unsigned short&>(hh[0])        |
                ((unsigned long long)reinterpret_cast<unsigned short&>(hh[1]) << 16) |
                ((unsigned long long)reinterpret_cast<unsigned short&>(hh[2]) << 32) |
                ((unsigned long long)reinterpret_cast<unsigned short&>(hh[3]) << 48);
            uint32_t laddr = sb + hp_st_off + (uint32_t)wbuf * 8192u;
#pragma unroll
            for (uint32_t tr = 0; tr < 4; tr++) dsmem_st_b64(laddr, tr, pk);
        }

        // ---- phase 4: cluster barrier ----
        CLUSTER_ARRIVE();
        CLUSTER_WAIT();
    }
}

// ---------------- head ----------------
__global__ void head_kernel(const float* __restrict__ hw, const float* __restrict__ hb,
                            float* __restrict__ out) {
    int t = blockIdx.x;
    int tid = threadIdx.x;
    int b  = tid & 31;
    int og = tid >> 5;
    const float* hf = g_HS + (size_t)(t * HID) * 32;
    const float* hr = g_HS + (size_t)((64 + t) * HID) * 32;
    float a0 = 0.f, a1 = 0.f, a2 = 0.f, a3 = 0.f;
    int o = og * 4;
    for (int h = 0; h < HID; h++) {
        float vf = __ldg(&hf[h * 32 + b]);
        float vr = __ldg(&hr[h * 32 + b]);
        a0 += vf * __ldg(&hw[(o + 0) * 512 + h]) + vr * __ldg(&hw[(o + 0) * 512 + 256 + h]);
        a1 += vf * __ldg(&hw[(o + 1) * 512 + h]) + vr * __ldg(&hw[(o + 1) * 512 + 256 + h]);
        a2 += vf * __ldg(&hw[(o + 2) * 512 + h]) + vr * __ldg(&hw[(o + 2) * 512 + 256 + h]);
        a3 += vf * __ldg(&hw[(o + 3) * 512 + h]) + vr * __ldg(&hw[(o + 3) * 512 + 256 + h]);
    }
    size_t base = ((size_t)b * 64 + t) * 32 + o;
    out[base + 0] = sigf(a0 + __ldg(&hb[o + 0]));
    out[base + 1] = sigf(a1 + __ldg(&hb[o + 1]));
    out[base + 2] = sigf(a2 + __ldg(&hb[o + 2]));
    out[base + 3] = sigf(a3 + __ldg(&hb[o + 3]));
}

// ---------------- launch ----------------
extern "C" void kernel_launch(void* const* d_in, const int* in_sizes, int n_in,
                              void* d_out, int out_size) {
    const int*   dialogue = (const int*)d_in[0];
    const float* emb   = (const float*)d_in[1];
    const float* w3    = (const float*)d_in[2];
    const float* b3    = (const float*)d_in[3];
    const float* w4    = (const float*)d_in[4];
    const float* b4    = (const float*)d_in[5];
    const float* w5    = (const float*)d_in[6];
    const float* b5    = (const float*)d_in[7];
    const float* wih_f = (const float*)d_in[8];
    const float* whh_f = (const float*)d_in[9];
    const float* bih_f = (const float*)d_in[10];
    const float* bhh_f = (const float*)d_in[11];
    const float* wih_r = (const float*)d_in[12];
    const float* whh_r = (const float*)d_in[13];
    const float* bih_r = (const float*)d_in[14];
    const float* bhh_r = (const float*)d_in[15];
    const float* hw    = (const float*)d_in[16];
    const float* hb    = (const float*)d_in[17];
    float* out = (float*)d_out;

    cudaFuncSetAttribute(pgemm_mma_kernel, cudaFuncAttributeMaxDynamicSharedMemorySize, 65536);
    cudaFuncSetAttribute(lstm_mma_kernel, cudaFuncAttributeMaxDynamicSharedMemorySize, LSM_BYTES);

    convA_kernel<<<(VOCAB * 160 + 255) / 256, 256>>>(emb);
    convB_kernel<<<(NPAD * 160 + 255) / 256, 256>>>(w3, w4, w5);

    dim3 gP(NTILES, MTILES);
    pgemm_mma_kernel<<<gP, 256, 65536>>>();

    conv_gather_kernel<<<BT, 64>>>(dialogue, b3, b4, b5);

    dim3 gX(16, 16, 2);
    xg_gemm_kernel<<<gX, 256>>>(wih_f, wih_r, bih_f, bhh_f, bih_r, bhh_r);

    lstm_mma_kernel<<<16, 256, LSM_BYTES>>>(whh_f, whh_r);

    head_kernel<<<TT, 256>>>(hw, hb, out);
}

// round 17
// speedup vs baseline: 1.5392x; 1.2209x over previous
#include <cuda_runtime.h>
#include <cuda_bf16.h>
#include <cuda_fp16.h>
#include <math.h>
#include <stdint.h>

#define VOCAB 32000
#define EMB   300
#define NFLT  100
#define HID   256
#define BB    32
#define TT    64
#define LL    48
#define NCOL  1200
#define BT    (BB*TT)

#define KTOT  320
#define NPAD  1280
#define MTILES 250
#define NTILES 10

// ---------------- device scratch ----------------
__device__ __align__(16) __half g_P[(size_t)VOCAB * NCOL];
__device__ __align__(16) __half g_A2[(size_t)VOCAB * KTOT];
__device__ __align__(16) __half g_B2[(size_t)NPAD * KTOT];
__device__ float g_rin[BT * 300];
__device__ float g_XG[2 * TT * 1024 * BB];
__device__ float g_HS[2 * TT * HID * BB];

__device__ __forceinline__ float sigf(float x) { return 1.0f / (1.0f + expf(-x)); }

__device__ __forceinline__ uint32_t smem_u32(const void* p) {
    uint32_t a;
    asm("{ .reg .u64 t; cvta.to.shared.u64 t, %1; cvt.u32.u64 %0, t; }" : "=r"(a) : "l"(p));
    return a;
}
#define CP_ASYNC16(d, s) asm volatile("cp.async.cg.shared.global [%0], [%1], 16;" :: "r"(d), "l"(s))
#define CP_COMMIT()      asm volatile("cp.async.commit_group;" ::: "memory")
#define CP_WAIT(n)       asm volatile("cp.async.wait_group %0;" :: "n"(n) : "memory")
#define LDMX4(r0, r1, r2, r3, addr) \
    asm volatile("ldmatrix.sync.aligned.m8n8.x4.shared.b16 {%0,%1,%2,%3}, [%4];" \
                 : "=r"(r0), "=r"(r1), "=r"(r2), "=r"(r3) : "r"(addr))
#define MMA16816H(c, a, b) \
    asm volatile("mma.sync.aligned.m16n8k16.row.col.f32.f16.f16.f32 " \
                 "{%0,%1,%2,%3}, {%4,%5,%6,%7}, {%8,%9}, {%0,%1,%2,%3};" \
                 : "+f"((c)[0]), "+f"((c)[1]), "+f"((c)[2]), "+f"((c)[3]) \
                 : "r"((a)[0]), "r"((a)[1]), "r"((a)[2]), "r"((a)[3]), "r"((b)[0]), "r"((b)[1]))

#define CLUSTER_ARRIVE() asm volatile("barrier.cluster.arrive.aligned;" ::: "memory")
#define CLUSTER_WAIT()   asm volatile("barrier.cluster.wait.aligned;" ::: "memory")

__device__ __forceinline__ void dsmem_st_b64(uint32_t laddr, uint32_t rank, unsigned long long v) {
    asm volatile(
        "{\n\t.reg .b32 ra;\n\t"
        "mapa.shared::cluster.u32 ra, %0, %1;\n\t"
        "st.shared::cluster.b64 [ra], %2;\n\t}"
        :: "r"(laddr), "r"(rank), "l"(v) : "memory");
}

// ---------------- build A2: fp16 emb rows, K padded to 320 ----------------
__global__ void convA_kernel(const float* __restrict__ emb) {
    int idx = blockIdx.x * blockDim.x + threadIdx.x;
    if (idx >= VOCAB * 160) return;
    int m  = idx / 160;
    int k2 = idx % 160;
    int k  = k2 * 2;
    float v0 = (k     < EMB) ? __ldg(&emb[(size_t)m * EMB + k])     : 0.0f;
    float v1 = (k + 1 < EMB) ? __ldg(&emb[(size_t)m * EMB + k + 1]) : 0.0f;
    ((__half2*)g_A2)[(size_t)m * 160 + k2] = __floats2half2_rn(v0, v1);
}

// ---------------- build B2: fp16 Wcat [n][k], K padded to 320 ----------------
__global__ void convB_kernel(const float* __restrict__ w3, const float* __restrict__ w4,
                             const float* __restrict__ w5) {
    int idx = blockIdx.x * blockDim.x + threadIdx.x;
    if (idx >= NPAD * 160) return;
    int n  = idx / 160;
    int k2 = idx % 160;
    int k0 = k2 * 2;
    float v0 = 0.0f, v1 = 0.0f;
    if (n < NCOL) {
        int c = n;
#pragma unroll
        for (int q = 0; q < 2; q++) {
            int k = k0 + q;
            float v = 0.0f;
            if (k < EMB) {
                if (c < 300)      { int fk = c / 100;        int nf = c % 100;        v = __ldg(&w3[((size_t)nf * EMB + k) * 3 + fk]); }
                else if (c < 700) { int c2 = c - 300; int fk = c2 / 100; int nf = c2 % 100; v = __ldg(&w4[((size_t)nf * EMB + k) * 4 + fk]); }
                else              { int c2 = c - 700; int fk = c2 / 100; int nf = c2 % 100; v = __ldg(&w5[((size_t)nf * EMB + k) * 5 + fk]); }
            }
            if (q == 0) v0 = v; else v1 = v;
        }
    }
    ((__half2*)g_B2)[(size_t)n * 160 + k2] = __floats2half2_rn(v0, v1);
}

// ---------------- fp16 HMMA GEMM (P): K=320, 5 k-iters ----------------
__device__ __forceinline__ void load_chunk(uint32_t sAb, uint32_t sBb, int bm, int bn,
                                           int kk, int tid) {
    const uint8_t* Ab = (const uint8_t*)g_A2;
    const uint8_t* Bb = (const uint8_t*)g_B2;
#pragma unroll
    for (int i = 0; i < 4; i++) {
        int id = tid + i * 256;
        int r = id >> 3, c = id & 7;
        uint32_t d = sAb + r * 128 + ((c ^ (r & 7)) << 4);
        CP_ASYNC16(d, Ab + (size_t)(bm + r) * (KTOT * 2) + kk * 2 + c * 16);
    }
#pragma unroll
    for (int i = 0; i < 4; i++) {
        int id = tid + i * 256;
        int r = id >> 3, c = id & 7;
        uint32_t d = sBb + r * 128 + ((c ^ (r & 7)) << 4);
        CP_ASYNC16(d, Bb + (size_t)(bn + r) * (KTOT * 2) + kk * 2 + c * 16);
    }
}

__global__ void __launch_bounds__(256, 2) pgemm_mma_kernel() {
    extern __shared__ __align__(128) uint8_t dyn[];
    uint32_t sbase = smem_u32(dyn);
    int tid  = threadIdx.x;
    int wid  = tid >> 5, lane = tid & 31;
    int m0   = (wid & 1) * 64;
    int n0   = (wid >> 1) * 32;
    int bm   = blockIdx.y * 128;
    int bn   = blockIdx.x * 128;

    float acc[4][4][4];
#pragma unroll
    for (int i = 0; i < 4; i++)
#pragma unroll
        for (int j = 0; j < 4; j++)
#pragma unroll
            for (int q = 0; q < 4; q++) acc[i][j][q] = 0.0f;

    load_chunk(sbase, sbase + 16384, bm, bn, 0, tid);
    CP_COMMIT();

#pragma unroll 1
    for (int it = 0; it < 5; it++) {
        if (it < 4) {
            uint32_t nb = sbase + ((it + 1) & 1) * 32768;
            load_chunk(nb, nb + 16384, bm, bn, (it + 1) * 64, tid);
            CP_COMMIT();
            CP_WAIT(1);
        } else {
            CP_WAIT(0);
        }
        __syncthreads();

        uint32_t sAb = sbase + (it & 1) * 32768;
        uint32_t sBb = sAb + 16384;
#pragma unroll
        for (int ks = 0; ks < 4; ks++) {
            uint32_t a[4][4];
#pragma unroll
            for (int mf = 0; mf < 4; mf++) {
                int row = m0 + mf * 16 + (lane & 15);
                int ch  = ks * 2 + (lane >> 4);
                uint32_t addr = sAb + row * 128 + ((ch ^ (row & 7)) << 4);
                LDMX4(a[mf][0], a[mf][1], a[mf][2], a[mf][3], addr);
            }
            uint32_t b[4][2];
#pragma unroll
            for (int p = 0; p < 2; p++) {
                int sel = lane >> 3;
                int row = n0 + p * 16 + ((sel >> 1) << 3) + (lane & 7);
                int ch  = ks * 2 + (sel & 1);
                uint32_t addr = sBb + row * 128 + ((ch ^ (row & 7)) << 4);
                uint32_t r0, r1, r2, r3;
                LDMX4(r0, r1, r2, r3, addr);
                b[p * 2][0] = r0; b[p * 2][1] = r1;
                b[p * 2 + 1][0] = r2; b[p * 2 + 1][1] = r3;
            }
#pragma unroll
            for (int mf = 0; mf < 4; mf++)
#pragma unroll
                for (int nf = 0; nf < 4; nf++)
                    MMA16816H(acc[mf][nf], a[mf], b[nf]);
        }
        __syncthreads();
    }

#pragma unroll
    for (int mf = 0; mf < 4; mf++) {
        int row0 = bm + m0 + mf * 16 + (lane >> 2);
#pragma unroll
        for (int nf = 0; nf < 4; nf++) {
            int col = bn + n0 + nf * 8 + 2 * (lane & 3);
            if (col < NCOL) {
                *(__half2*)(g_P + (size_t)row0 * NCOL + col) =
                    __floats2half2_rn(acc[mf][nf][0], acc[mf][nf][1]);
                *(__half2*)(g_P + (size_t)(row0 + 8) * NCOL + col) =
                    __floats2half2_rn(acc[mf][nf][2], acc[mf][nf][3]);
            }
        }
    }
}

// ---------------- conv gather (fp16 P, half2 per thread) ----------------
__global__ void conv_gather_kernel(const int* __restrict__ dia,
                                   const float* __restrict__ b3,
                                   const float* __restrict__ b4,
                                   const float* __restrict__ b5) {
    int bt = blockIdx.x;
    __shared__ int tok[LL];
    int tid = threadIdx.x;
    if (tid < LL) tok[tid] = dia[bt * LL + tid] * NCOL;
    __syncthreads();
    if (tid >= 50) return;
    int nf = tid * 2;
    const __half* P = g_P;

    float mx3 = -1e30f, my3 = -1e30f;
    for (int p = 0; p < 46; p++) {
        float2 a = __half22float2(*(const __half2*)(P + (size_t)tok[p]     + nf));
        float2 b = __half22float2(*(const __half2*)(P + (size_t)tok[p + 1] + 100 + nf));
        float2 c = __half22float2(*(const __half2*)(P + (size_t)tok[p + 2] + 200 + nf));
        mx3 = fmaxf(mx3, a.x + b.x + c.x);
        my3 = fmaxf(my3, a.y + b.y + c.y);
    }
    g_rin[bt * 300 + nf]     = fmaxf(mx3 + b3[nf], 0.0f);
    g_rin[bt * 300 + nf + 1] = fmaxf(my3 + b3[nf + 1], 0.0f);

    float mx4 = -1e30f, my4 = -1e30f;
    for (int p = 0; p < 45; p++) {
        float2 a = __half22float2(*(const __half2*)(P + (size_t)tok[p]     + 300 + nf));
        float2 b = __half22float2(*(const __half2*)(P + (size_t)tok[p + 1] + 400 + nf));
        float2 c = __half22float2(*(const __half2*)(P + (size_t)tok[p + 2] + 500 + nf));
        float2 d = __half22float2(*(const __half2*)(P + (size_t)tok[p + 3] + 600 + nf));
        mx4 = fmaxf(mx4, a.x + b.x + c.x + d.x);
        my4 = fmaxf(my4, a.y + b.y + c.y + d.y);
    }
    g_rin[bt * 300 + 100 + nf]     = fmaxf(mx4 + b4[nf], 0.0f);
    g_rin[bt * 300 + 100 + nf + 1] = fmaxf(my4 + b4[nf + 1], 0.0f);

    float mx5 = -1e30f, my5 = -1e30f;
    for (int p = 0; p < 44; p++) {
        float2 a = __half22float2(*(const __half2*)(P + (size_t)tok[p]     + 700 + nf));
        float2 b = __half22float2(*(const __half2*)(P + (size_t)tok[p + 1] + 800 + nf));
        float2 c = __half22float2(*(const __half2*)(P + (size_t)tok[p + 2] + 900 + nf));
        float2 d = __half22float2(*(const __half2*)(P + (size_t)tok[p + 3] + 1000 + nf));
        float2 e = __half22float2(*(const __half2*)(P + (size_t)tok[p + 4] + 1100 + nf));
        mx5 = fmaxf(mx5, a.x + b.x + c.x + d.x + e.x);
        my5 = fmaxf(my5, a.y + b.y + c.y + d.y + e.y);
    }
    g_rin[bt * 300 + 200 + nf]     = fmaxf(mx5 + b5[nf], 0.0f);
    g_rin[bt * 300 + 200 + nf + 1] = fmaxf(my5 + b5[nf + 1], 0.0f);
}

// ---------------- xg GEMM ----------------
__global__ void xg_gemm_kernel(const float* __restrict__ wih_f, const float* __restrict__ wih_r,
                               const float* __restrict__ bih_f, const float* __restrict__ bhh_f,
                               const float* __restrict__ bih_r, const float* __restrict__ bhh_r) {
    const int K = 300;
    __shared__ float sA[16][132];
    __shared__ float sB[16][68];
    int dir = blockIdx.z;
    const float* W  = dir ? wih_r : wih_f;
    const float* bi = dir ? bih_r : bih_f;
    const float* bh = dir ? bhh_r : bhh_f;
    int bm = blockIdx.y * 128;
    int bn = blockIdx.x * 64;
    int tid = threadIdx.x;
    int tx = tid & 15, ty = tid >> 4;
    float acc[8][4] = {};
    for (int kk = 0; kk < K; kk += 16) {
        int ak = tid & 15, am = tid >> 4;
        int gk = kk + ak;
#pragma unroll
        for (int i = 0; i < 8; i++) {
            int m  = am + i * 16;
            int gm = bm + m;
            int t  = gm >> 5, bb = gm & 31;
            int st = dir ? (63 - t) : t;
            sA[ak][m] = (gk < K) ? __ldg(&g_rin[(bb * 64 + st) * 300 + gk]) : 0.0f;
        }
        int wk = tid & 15, wn = tid >> 4;
#pragma unroll
        for (int i = 0; i < 4; i++) {
            int n   = wn + i * 16;
            int gkb = kk + wk;
            sB[wk][n] = (gkb < K) ? __ldg(&W[(bn + n) * 300 + gkb]) : 0.0f;
        }
        __syncthreads();
#pragma unroll
        for (int k = 0; k < 16; k++) {
            float4 a0 = *(const float4*)&sA[k][ty * 8];
            float4 a1 = *(const float4*)&sA[k][ty * 8 + 4];
            float4 b0 = *(const float4*)&sB[k][tx * 4];
            float ra[8] = {a0.x, a0.y, a0.z, a0.w, a1.x, a1.y, a1.z, a1.w};
            float rb[4] = {b0.x, b0.y, b0.z, b0.w};
#pragma unroll
            for (int i = 0; i < 8; i++)
#pragma unroll
                for (int j = 0; j < 4; j++) acc[i][j] += ra[i] * rb[j];
        }
        __syncthreads();
    }
#pragma unroll
    for (int i = 0; i < 8; i++) {
        int gm = bm + ty * 8 + i;
        int t = gm >> 5, bb = gm & 31;
#pragma unroll
        for (int j = 0; j < 4; j++) {
            int g = bn + tx * 4 + j;
            g_XG[(((size_t)dir * 64 + t) * 1024 + g) * 32 + bb] =
                acc[i][j] + __ldg(&bi[g]) + __ldg(&bh[g]);
        }
    }
}

// ================= fp16 HMMA cluster BiLSTM v4 (R16, proven) =================
#define LOFF_W    0
#define LOFF_HP   131072
#define LOFF_SG   147456
#define LSM_BYTES 164352

__device__ __forceinline__ uint32_t w_off16(int row, int chunk, int k) {
    int byte = k * 2;
    int c16  = byte >> 4;
    return (uint32_t)(LOFF_W + chunk * 32768 + row * 128 + (((c16 ^ (row & 7)) << 4) | (byte & 15)));
}

__global__ void __launch_bounds__(256, 1) __cluster_dims__(4, 1, 1)
lstm_mma_kernel(const float* __restrict__ whh_f, const float* __restrict__ whh_r) {
    extern __shared__ __align__(128) uint8_t lsm[];
    uint32_t sb = smem_u32(lsm);
    float* sG = (float*)(lsm + LOFF_SG);

    int tid = threadIdx.x;
    int w   = tid >> 5, lane = tid & 31;
    uint32_t rank;
    asm("mov.u32 %0, %%cluster_ctarank;" : "=r"(rank));
    int cid = blockIdx.x >> 2;
    int dir = cid >> 1;
    int bg  = cid & 1;
    int j0  = (int)rank * 64;
    const float* whh = dir ? whh_r : whh_f;
    const float* xg_glob = g_XG;

    for (int idx = tid; idx < 65536; idx += 256) {
        int row = idx >> 8;
        int k   = idx & 255;
        int jl = row >> 2, g = row & 3;
        float v = __ldg(&whh[(size_t)(g * 256 + j0 + jl) * 256 + k]);
        *(__half*)(lsm + w_off16(row, k >> 6, k & 63)) = __float2half(v);
    }
    for (int i = tid; i < 16384 / 4; i += 256) ((uint32_t*)(lsm + LOFF_HP))[i] = 0;
    __syncthreads();
    CLUSTER_ARRIVE();
    CLUSTER_WAIT();

    int n0 = w * 32;

    int fb  = tid & 15;
    int jlg = tid >> 4;
    int gb  = bg * 16 + fb;
    float cst[4] = {0.0f, 0.0f, 0.0f, 0.0f};

    int byte0 = jlg * 8;
    uint32_t hp_st_off = (uint32_t)(LOFF_HP + (int)rank * 2048 + fb * 128 +
                                    ((((byte0 >> 4) ^ (fb & 7)) << 4) | (byte0 & 15)));

    for (int s = 0; s < 64; s++) {
        int rbuf = s & 1;
        int wbuf = rbuf ^ 1;

        float xg[4][4];
        {
            size_t xbase = (((size_t)dir * 64 + s) * 1024) * 32;
#pragma unroll
            for (int pp = 0; pp < 4; pp++) {
                int gj = j0 + jlg * 4 + pp;
#pragma unroll
                for (int g = 0; g < 4; g++)
                    xg[pp][g] = __ldg(&xg_glob[xbase + (size_t)(g * 256 + gj) * 32 + gb]);
            }
        }

        float acc[4][4];
#pragma unroll
        for (int nf = 0; nf < 4; nf++)
#pragma unroll
            for (int q = 0; q < 4; q++) acc[nf][q] = 0.0f;

#pragma unroll
        for (int cc = 0; cc < 4; cc++) {
            uint32_t wbase = sb + LOFF_W + cc * 32768;
            uint32_t hbase = sb + LOFF_HP + rbuf * 8192 + cc * 2048;
#pragma unroll
            for (int ks = 0; ks < 4; ks++) {
                uint32_t a[4];
                {
                    int row = lane & 15;
                    int ch  = ks * 2 + (lane >> 4);
                    uint32_t addr = hbase + row * 128 + ((ch ^ (row & 7)) << 4);
                    LDMX4(a[0], a[1], a[2], a[3], addr);
                }
                uint32_t b[4][2];
#pragma unroll
                for (int p = 0; p < 2; p++) {
                    int sel = lane >> 3;
                    int row = n0 + p * 16 + ((sel >> 1) << 3) + (lane & 7);
                    int ch  = ks * 2 + (sel & 1);
                    uint32_t addr = wbase + row * 128 + ((ch ^ (row & 7)) << 4);
                    uint32_t r0, r1, r2, r3;
                    LDMX4(r0, r1, r2, r3, addr);
                    b[p * 2][0] = r0; b[p * 2][1] = r1;
                    b[p * 2 + 1][0] = r2; b[p * 2 + 1][1] = r3;
                }
#pragma unroll
                for (int nf = 0; nf < 4; nf++)
                    MMA16816H(acc[nf], a, b[nf]);
            }
        }

        {
            int rowb = lane >> 2;
            int colb = n0 + 2 * (lane & 3);
#pragma unroll
            for (int nf = 0; nf < 4; nf++) {
                int col = colb + nf * 8;
                sG[rowb * 264 + col]           = acc[nf][0];
                sG[rowb * 264 + col + 1]       = acc[nf][1];
                sG[(rowb + 8) * 264 + col]     = acc[nf][2];
                sG[(rowb + 8) * 264 + col + 1] = acc[nf][3];
            }
        }
        __syncthreads();

        {
            __half hh[4];
            int tout = dir ? (63 - s) : s;
#pragma unroll
            for (int pp = 0; pp < 4; pp++) {
                int jl = jlg * 4 + pp;
                const float* gr = sG + fb * 264 + jl * 4;
                float ai = gr[0] + xg[pp][0];
                float af = gr[1] + xg[pp][1];
                float ag = gr[2] + xg[pp][2];
                float ao = gr[3] + xg[pp][3];
                float iv = sigf(ai), fv = sigf(af), gv = tanhf(ag), ov = sigf(ao);
                cst[pp] = fv * cst[pp] + iv * gv;
                float h = ov * tanhf(cst[pp]);
                hh[pp] = __float2half(h);
                g_HS[(((size_t)dir * 64 + tout) * HID + (j0 + jl)) * 32 + gb] = h;
            }
            unsigned long long pk =
                (unsigned long long)reinterpret_cast<unsigned short&>(hh[0])        |
                ((unsigned long long)reinterpret_cast<unsigned short&>(hh[1]) << 16) |
                ((unsigned long long)reinterpret_cast<unsigned short&>(hh[2]) << 32) |
                ((unsigned long long)reinterpret_cast<unsigned short&>(hh[3]) << 48);
            uint32_t laddr = sb + hp_st_off + (uint32_t)wbuf * 8192u;
#pragma unroll
            for (uint32_t tr = 0; tr < 4; tr++) dsmem_st_b64(laddr, tr, pk);
        }

        CLUSTER_ARRIVE();
        CLUSTER_WAIT();
    }
}

// ---------------- head ----------------
__global__ void head_kernel(const float* __restrict__ hw, const float* __restrict__ hb,
                            float* __restrict__ out) {
    int t = blockIdx.x;
    int tid = threadIdx.x;
    int b  = tid & 31;
    int og = tid >> 5;
    const float* hf = g_HS + (size_t)(t * HID) * 32;
    const float* hr = g_HS + (size_t)((64 + t) * HID) * 32;
    float a0 = 0.f, a1 = 0.f, a2 = 0.f, a3 = 0.f;
    int o = og * 4;
    for (int h = 0; h < HID; h++) {
        float vf = __ldg(&hf[h * 32 + b]);
        float vr = __ldg(&hr[h * 32 + b]);
        a0 += vf * __ldg(&hw[(o + 0) * 512 + h]) + vr * __ldg(&hw[(o + 0) * 512 + 256 + h]);
        a1 += vf * __ldg(&hw[(o + 1) * 512 + h]) + vr * __ldg(&hw[(o + 1) * 512 + 256 + h]);
        a2 += vf * __ldg(&hw[(o + 2) * 512 + h]) + vr * __ldg(&hw[(o + 2) * 512 + 256 + h]);
        a3 += vf * __ldg(&hw[(o + 3) * 512 + h]) + vr * __ldg(&hw[(o + 3) * 512 + 256 + h]);
    }
    size_t base = ((size_t)b * 64 + t) * 32 + o;
    out[base + 0] = sigf(a0 + __ldg(&hb[o + 0]));
    out[base + 1] = sigf(a1 + __ldg(&hb[o + 1]));
    out[base + 2] = sigf(a2 + __ldg(&hb[o + 2]));
    out[base + 3] = sigf(a3 + __ldg(&hb[o + 3]));
}

// ---------------- launch ----------------
extern "C" void kernel_launch(void* const* d_in, const int* in_sizes, int n_in,
                              void* d_out, int out_size) {
    const int*   dialogue = (const int*)d_in[0];
    const float* emb   = (const float*)d_in[1];
    const float* w3    = (const float*)d_in[2];
    const float* b3    = (const float*)d_in[3];
    const float* w4    = (const float*)d_in[4];
    const float* b4    = (const float*)d_in[5];
    const float* w5    = (const float*)d_in[6];
    const float* b5    = (const float*)d_in[7];
    const float* wih_f = (const float*)d_in[8];
    const float* whh_f = (const float*)d_in[9];
    const float* bih_f = (const float*)d_in[10];
    const float* bhh_f = (const float*)d_in[11];
    const float* wih_r = (const float*)d_in[12];
    const float* whh_r = (const float*)d_in[13];
    const float* bih_r = (const float*)d_in[14];
    const float* bhh_r = (const float*)d_in[15];
    const float* hw    = (const float*)d_in[16];
    const float* hb    = (const float*)d_in[17];
    float* out = (float*)d_out;

    cudaFuncSetAttribute(pgemm_mma_kernel, cudaFuncAttributeMaxDynamicSharedMemorySize, 65536);
    cudaFuncSetAttribute(lstm_mma_kernel, cudaFuncAttributeMaxDynamicSharedMemorySize, LSM_BYTES);

    convA_kernel<<<(VOCAB * 160 + 255) / 256, 256>>>(emb);
    convB_kernel<<<(NPAD * 160 + 255) / 256, 256>>>(w3, w4, w5);

    dim3 gP(NTILES, MTILES);
    pgemm_mma_kernel<<<gP, 256, 65536>>>();

    conv_gather_kernel<<<BT, 64>>>(dialogue, b3, b4, b5);

    dim3 gX(16, 16, 2);
    xg_gemm_kernel<<<gX, 256>>>(wih_f, wih_r, bih_f, bhh_f, bih_r, bhh_r);

    lstm_mma_kernel<<<16, 256, LSM_BYTES>>>(whh_f, whh_r);

    head_kernel<<<TT, 256>>>(hw, hb, out);
}